// round 1
// baseline (speedup 1.0000x reference)
#include <cuda_runtime.h>

// Problem constants (MusicgenAttention: B=2, T=2048, D=1024, H=16, HD=64)
#define B_   2
#define T_   2048
#define D_   1024
#define H_   16
#define HD_  64
#define M_   (B_ * T_)          // 4096 rows for the projections

// Scratch (device globals — allocation-free per harness rules)
__device__ float g_Q[B_ * H_ * T_ * HD_];   // 16 MB, [B,H,T,HD]
__device__ float g_K[B_ * H_ * T_ * HD_];   // 16 MB
__device__ float g_V[B_ * H_ * T_ * HD_];   // 16 MB
__device__ float g_Ctx[B_ * T_ * D_];       // 16 MB, [B,T,D]

// ---------------------------------------------------------------------------
// GEMM: C = (A @ W^T + bias) * scale
//   A: [M_, 1024] row-major; W: [1024, 1024] row-major (nn.Linear weight)
//   MODE 0: C[m*1024 + n]                      (plain [B,T,D])
//   MODE 1: C[((b*H + h)*T + t)*HD + d]        (split into [B,H,T,HD])
// 128x128 tile, BK=8, 256 threads, 8x8 per thread.
// ---------------------------------------------------------------------------
template <int MODE>
__global__ __launch_bounds__(256)
void gemm_bias_kernel(const float* __restrict__ A,
                      const float* __restrict__ W,
                      const float* __restrict__ bias,
                      float* __restrict__ C,
                      float scale)
{
    const int K = D_;
    __shared__ float As[8][128];
    __shared__ float Ws[8][128];

    const int tid = threadIdx.x;
    const int m0 = blockIdx.y * 128;
    const int n0 = blockIdx.x * 128;
    const int tx = tid & 15;     // n direction (16)
    const int ty = tid >> 4;     // m direction (16)

    float acc[8][8];
#pragma unroll
    for (int i = 0; i < 8; i++)
#pragma unroll
        for (int j = 0; j < 8; j++) acc[i][j] = 0.f;

    const int lrow  = tid >> 1;        // 0..127
    const int lpart = (tid & 1) * 4;   // 0 or 4
    const float* Aptr = A + (size_t)(m0 + lrow) * K + lpart;
    const float* Wptr = W + (size_t)(n0 + lrow) * K + lpart;

    for (int k0 = 0; k0 < K; k0 += 8) {
        const float4 av = *(const float4*)(Aptr + k0);
        const float4 wv = *(const float4*)(Wptr + k0);
        __syncthreads();
        As[lpart + 0][lrow] = av.x; As[lpart + 1][lrow] = av.y;
        As[lpart + 2][lrow] = av.z; As[lpart + 3][lrow] = av.w;
        Ws[lpart + 0][lrow] = wv.x; Ws[lpart + 1][lrow] = wv.y;
        Ws[lpart + 2][lrow] = wv.z; Ws[lpart + 3][lrow] = wv.w;
        __syncthreads();

#pragma unroll
        for (int kk = 0; kk < 8; kk++) {
            const float4 a0 = *(const float4*)&As[kk][ty * 8];
            const float4 a1 = *(const float4*)&As[kk][ty * 8 + 4];
            const float4 b0 = *(const float4*)&Ws[kk][tx * 8];
            const float4 b1 = *(const float4*)&Ws[kk][tx * 8 + 4];
            const float a[8] = {a0.x, a0.y, a0.z, a0.w, a1.x, a1.y, a1.z, a1.w};
            const float b[8] = {b0.x, b0.y, b0.z, b0.w, b1.x, b1.y, b1.z, b1.w};
#pragma unroll
            for (int i = 0; i < 8; i++)
#pragma unroll
                for (int j = 0; j < 8; j++)
                    acc[i][j] += a[i] * b[j];
        }
    }

#pragma unroll
    for (int i = 0; i < 8; i++) {
        const int m = m0 + ty * 8 + i;
#pragma unroll
        for (int j = 0; j < 8; j++) {
            const int n = n0 + tx * 8 + j;
            const float v = (acc[i][j] + bias[n]) * scale;
            if (MODE == 0) {
                C[(size_t)m * D_ + n] = v;
            } else {
                const int b = m >> 11;        // m / T_
                const int t = m & (T_ - 1);
                const int h = n >> 6;         // n / HD_
                const int d = n & (HD_ - 1);
                C[(((size_t)(b * H_ + h) * T_) + t) * HD_ + d] = v;
            }
        }
    }
}

// ---------------------------------------------------------------------------
// Flash attention: each thread owns one query row (q[64], o[64] in registers),
// K/V tiles of 64 keys staged in smem, online softmax per thread.
// Grid: (T/128, H, B), 128 threads.
// Writes context directly in [B,T,D] layout.
// ---------------------------------------------------------------------------
__global__ __launch_bounds__(128)
void attn_kernel(const float* __restrict__ Q,
                 const float* __restrict__ K,
                 const float* __restrict__ V,
                 const float* __restrict__ mask,
                 float* __restrict__ Ctx)
{
    __shared__ float Ks[64 * 64];
    __shared__ float Vs[64 * 64];

    const int tid = threadIdx.x;
    const int b = blockIdx.z;
    const int h = blockIdx.y;
    const int t = blockIdx.x * 128 + tid;

    const size_t head_base = (size_t)(b * H_ + h) * T_ * HD_;
    const float* qrow = Q + head_base + (size_t)t * HD_;

    float q[64], o[64];
#pragma unroll
    for (int i = 0; i < 16; i++) {
        const float4 v4 = ((const float4*)qrow)[i];
        q[4 * i + 0] = v4.x; q[4 * i + 1] = v4.y;
        q[4 * i + 2] = v4.z; q[4 * i + 3] = v4.w;
    }
#pragma unroll
    for (int d = 0; d < 64; d++) o[d] = 0.f;

    float m_i = -1e30f;
    float l   = 0.f;

    const float* maskrow = mask + ((size_t)b * T_ + t) * T_;
    const float* Kbase = K + head_base;
    const float* Vbase = V + head_base;

    for (int kt = 0; kt < T_ / 64; kt++) {
        const int j0 = kt * 64;
        __syncthreads();
        {
            const float4* ksrc = (const float4*)(Kbase + (size_t)j0 * HD_);
            const float4* vsrc = (const float4*)(Vbase + (size_t)j0 * HD_);
            float4* kdst = (float4*)Ks;
            float4* vdst = (float4*)Vs;
#pragma unroll
            for (int i = 0; i < 8; i++) {
                kdst[tid + i * 128] = ksrc[tid + i * 128];
                vdst[tid + i * 128] = vsrc[tid + i * 128];
            }
        }
        __syncthreads();

#pragma unroll 1
        for (int jj = 0; jj < 64; jj += 4) {
            const float4 mv = *(const float4*)(maskrow + j0 + jj);
            const float mk[4] = {mv.x, mv.y, mv.z, mv.w};
#pragma unroll
            for (int u = 0; u < 4; u++) {
                const int j = jj + u;
                const float4* kr = (const float4*)(Ks + j * 64);
                float s = mk[u];
#pragma unroll
                for (int d4 = 0; d4 < 16; d4++) {
                    const float4 kv = kr[d4];
                    s += q[4 * d4 + 0] * kv.x + q[4 * d4 + 1] * kv.y
                       + q[4 * d4 + 2] * kv.z + q[4 * d4 + 3] * kv.w;
                }
                float p;
                if (s > m_i) {
                    const float corr = __expf(m_i - s);
                    l *= corr;
#pragma unroll
                    for (int d = 0; d < 64; d++) o[d] *= corr;
                    m_i = s;
                    p = 1.f;
                } else {
                    p = __expf(s - m_i);
                }
                l += p;
                const float4* vr = (const float4*)(Vs + j * 64);
#pragma unroll
                for (int d4 = 0; d4 < 16; d4++) {
                    const float4 vv = vr[d4];
                    o[4 * d4 + 0] += p * vv.x;
                    o[4 * d4 + 1] += p * vv.y;
                    o[4 * d4 + 2] += p * vv.z;
                    o[4 * d4 + 3] += p * vv.w;
                }
            }
        }
    }

    const float inv = 1.f / l;
    float* orow = Ctx + ((size_t)b * T_ + t) * D_ + h * HD_;
#pragma unroll
    for (int i = 0; i < 16; i++) {
        ((float4*)orow)[i] = make_float4(o[4 * i + 0] * inv, o[4 * i + 1] * inv,
                                         o[4 * i + 2] * inv, o[4 * i + 3] * inv);
    }
}

// ---------------------------------------------------------------------------
// Launch
// ---------------------------------------------------------------------------
extern "C" void kernel_launch(void* const* d_in, const int* in_sizes, int n_in,
                              void* d_out, int out_size)
{
    const float* hs   = (const float*)d_in[0];
    const float* mask = (const float*)d_in[1];
    const float* Wq   = (const float*)d_in[2];
    const float* bq   = (const float*)d_in[3];
    const float* Wk   = (const float*)d_in[4];
    const float* bk   = (const float*)d_in[5];
    const float* Wv   = (const float*)d_in[6];
    const float* bv   = (const float*)d_in[7];
    const float* Wo   = (const float*)d_in[8];
    const float* bo   = (const float*)d_in[9];
    float* out = (float*)d_out;

    float *Qd, *Kd, *Vd, *Ctxd;
    cudaGetSymbolAddress((void**)&Qd,   g_Q);
    cudaGetSymbolAddress((void**)&Kd,   g_K);
    cudaGetSymbolAddress((void**)&Vd,   g_V);
    cudaGetSymbolAddress((void**)&Ctxd, g_Ctx);

    const dim3 gemmGrid(D_ / 128, M_ / 128);   // (8, 32)
    const float scaling = 0.125f;              // HD^-0.5 = 64^-0.5

    gemm_bias_kernel<1><<<gemmGrid, 256>>>(hs, Wq, bq, Qd, scaling);
    gemm_bias_kernel<1><<<gemmGrid, 256>>>(hs, Wk, bk, Kd, 1.f);
    gemm_bias_kernel<1><<<gemmGrid, 256>>>(hs, Wv, bv, Vd, 1.f);

    attn_kernel<<<dim3(T_ / 128, H_, B_), 128>>>(Qd, Kd, Vd, mask, Ctxd);

    gemm_bias_kernel<0><<<gemmGrid, 256>>>(Ctxd, Wo, bo, out, 1.f);
}

// round 4
// speedup vs baseline: 1.3215x; 1.3215x over previous
#include <cuda_runtime.h>
#include <cuda_bf16.h>
#include <cstdint>

// Problem constants (MusicgenAttention: B=2, T=2048, D=1024, H=16, HD=64)
#define B_   2
#define T_   2048
#define D_   1024
#define H_   16
#define HD_  64
#define M_   (B_ * T_)          // 4096 rows for the projections

// Scratch (device globals — allocation-free per harness rules)
__device__ float g_Q[B_ * H_ * T_ * HD_];   // [B,H,T,HD]
__device__ float g_K[B_ * H_ * T_ * HD_];
__device__ float g_V[B_ * H_ * T_ * HD_];
__device__ float g_Ctx[B_ * T_ * D_];       // [B,T,D]

// ---------------------------------------------------------------------------
// Warp-MMA helpers (base sm_80+ PTX — no 'a'-features; tcgen05 is rejected by
// this toolchain's ptxas which targets plain sm_103)
// ---------------------------------------------------------------------------
__device__ __forceinline__ uint32_t smem_u32(const void* p) {
    uint32_t a;
    asm("{ .reg .u64 t; cvta.to.shared.u64 t, %1; cvt.u32.u64 %0, t; }" : "=r"(a) : "l"(p));
    return a;
}

#define LDMATRIX_X4(r, addr)                                                   \
    asm volatile("ldmatrix.sync.aligned.m8n8.x4.shared.b16 {%0,%1,%2,%3}, [%4];" \
        : "=r"((r)[0]), "=r"((r)[1]), "=r"((r)[2]), "=r"((r)[3]) : "r"(addr))

#define MMA_BF16(d, a, b0, b1)                                                 \
    asm volatile("mma.sync.aligned.m16n8k16.row.col.f32.bf16.bf16.f32 "        \
        "{%0,%1,%2,%3}, {%4,%5,%6,%7}, {%8,%9}, {%0,%1,%2,%3};"                \
        : "+f"((d)[0]), "+f"((d)[1]), "+f"((d)[2]), "+f"((d)[3])               \
        : "r"((a)[0]), "r"((a)[1]), "r"((a)[2]), "r"((a)[3]), "r"(b0), "r"(b1))

// smem tile: 128 rows x 32 bf16 (64B rows), chunk = 16B.
// swizzled byte offset for (row r, 16B-chunk c): conflict-free for the 8-lane
// ldmatrix phases and the 8-lane STS.128 phases.
__device__ __forceinline__ uint32_t swz(int r, int c) {
    return (uint32_t)(r * 64 + ((c ^ ((r >> 1) & 3)) << 4));
}

// ---------------------------------------------------------------------------
// bf16 MMA GEMM: C = (A @ W^T + bias) * scale, fp32 in/out, 3-term bf16 split.
//   A: [M_,1024], W: [1024,1024] row-major (nn.Linear weight)
// CTA tile 128x128, BK=32, 256 threads; warp grid 4(m) x 2(n), warp tile 32x64.
//   MODE 0: C[m*D_+n];  MODE 1: C[((b*H+h)*T+t)*HD+d]
// ---------------------------------------------------------------------------
#define BK 32
#define NITER (D_ / BK)            // 32
#define TILE_B  (128 * BK * 2)     // 8192 bytes per bf16 tile
#define STAGE_B (4 * TILE_B)       // Ah, Al, Wh, Wl = 32 KB
#define GEMM_SMEM (2 * STAGE_B)    // 64 KB

__device__ __forceinline__ void cvt_split8(const float* f, uint4& hi, uint4& lo) {
    uint32_t h[4], l[4];
#pragma unroll
    for (int i = 0; i < 4; i++) {
        __nv_bfloat162 hb = __float22bfloat162_rn(make_float2(f[2 * i], f[2 * i + 1]));
        float2 hf = __bfloat1622float2(hb);
        __nv_bfloat162 lb = __float22bfloat162_rn(
            make_float2(f[2 * i] - hf.x, f[2 * i + 1] - hf.y));
        h[i] = *(uint32_t*)&hb;
        l[i] = *(uint32_t*)&lb;
    }
    hi = make_uint4(h[0], h[1], h[2], h[3]);
    lo = make_uint4(l[0], l[1], l[2], l[3]);
}

template <int MODE>
__global__ __launch_bounds__(256)
void gemm_mma(const float* __restrict__ A, const float* __restrict__ W,
              const float* __restrict__ bias, float* __restrict__ C, float scale)
{
    extern __shared__ char smem[];
    const uint32_t sbase = smem_u32(smem);

    const int tid = threadIdx.x;
    const int wid = tid >> 5;
    const int l   = tid & 31;
    const int m0 = blockIdx.y * 128;
    const int n0 = blockIdx.x * 128;
    const int wm = (wid >> 1) * 32;       // warp m-offset in tile
    const int wn = (wid & 1) * 64;        // warp n-offset in tile

    float acc[2][8][4];
#pragma unroll
    for (int i = 0; i < 2; i++)
#pragma unroll
        for (int j = 0; j < 8; j++)
#pragma unroll
            for (int c = 0; c < 4; c++) acc[i][j][c] = 0.f;

    // per-thread global-load assignment: chunks 2*tid, 2*tid+1 (chunk = 8 floats)
    const int ch0 = tid * 2;
    const int lr  = ch0 >> 2;             // row 0..127
    const int lc0 = ch0 & 3;              // chunk col 0 or 2

    float abuf[16], wbuf[16];

    // ---- load iter 0 ----
    {
        const float* Ar = A + (size_t)(m0 + lr) * D_ + lc0 * 8;
        const float* Wr = W + (size_t)(n0 + lr) * D_ + lc0 * 8;
#pragma unroll
        for (int u = 0; u < 4; u++) {
            *(float4*)(abuf + u * 4) = *(const float4*)(Ar + u * 4);
            *(float4*)(wbuf + u * 4) = *(const float4*)(Wr + u * 4);
        }
    }

    for (int it = 0; it < NITER; it++) {
        const int s = it & 1;
        const uint32_t stage = sbase + s * STAGE_B;

        // store current regs -> stage s
        {
            char* st = smem + s * STAGE_B;
#pragma unroll
            for (int u = 0; u < 2; u++) {
                const uint32_t sw = swz(lr, lc0 + u);
                uint4 hi, lo;
                cvt_split8(abuf + u * 8, hi, lo);
                *(uint4*)(st + sw)          = hi;     // Ah
                *(uint4*)(st + TILE_B + sw) = lo;     // Al
                cvt_split8(wbuf + u * 8, hi, lo);
                *(uint4*)(st + 2 * TILE_B + sw) = hi; // Wh
                *(uint4*)(st + 3 * TILE_B + sw) = lo; // Wl
            }
        }
        __syncthreads();

        // prefetch next iter into regs (overlaps with MMA below)
        if (it + 1 < NITER) {
            const int k0 = (it + 1) * BK;
            const float* Ar = A + (size_t)(m0 + lr) * D_ + k0 + lc0 * 8;
            const float* Wr = W + (size_t)(n0 + lr) * D_ + k0 + lc0 * 8;
#pragma unroll
            for (int u = 0; u < 4; u++) {
                *(float4*)(abuf + u * 4) = *(const float4*)(Ar + u * 4);
                *(float4*)(wbuf + u * 4) = *(const float4*)(Wr + u * 4);
            }
        }

        // ---- compute on stage s ----
        const uint32_t AhU = stage;
        const uint32_t AlU = stage + TILE_B;
        const uint32_t WhU = stage + 2 * TILE_B;
        const uint32_t WlU = stage + 3 * TILE_B;

#pragma unroll
        for (int ks = 0; ks < 2; ks++) {
            const int c0 = ks * 2;

            // A fragments (hi & lo) for both m16 tiles
            uint32_t afh[2][4], afl[2][4];
            {
                const int rA = wm + (l & 7) + ((l >> 3) & 1) * 8;
                const int cA = c0 + (l >> 4);
#pragma unroll
                for (int i = 0; i < 2; i++) {
                    const uint32_t off = swz(rA + i * 16, cA);
                    LDMATRIX_X4(afh[i], AhU + off);
                    LDMATRIX_X4(afl[i], AlU + off);
                }
            }

#pragma unroll
            for (int jp = 0; jp < 4; jp++) {
                const int rB = wn + jp * 16 + (l & 7) + ((l >> 4) & 1) * 8;
                const int cB = c0 + ((l >> 3) & 1);
                const uint32_t off = swz(rB, cB);
                uint32_t bh[4], bl[4];
                LDMATRIX_X4(bh, WhU + off);
                LDMATRIX_X4(bl, WlU + off);
#pragma unroll
                for (int i = 0; i < 2; i++) {
                    MMA_BF16(acc[i][jp * 2],     afh[i], bh[0], bh[1]);
                    MMA_BF16(acc[i][jp * 2],     afl[i], bh[0], bh[1]);
                    MMA_BF16(acc[i][jp * 2],     afh[i], bl[0], bl[1]);
                    MMA_BF16(acc[i][jp * 2 + 1], afh[i], bh[2], bh[3]);
                    MMA_BF16(acc[i][jp * 2 + 1], afl[i], bh[2], bh[3]);
                    MMA_BF16(acc[i][jp * 2 + 1], afh[i], bl[2], bl[3]);
                }
            }
        }
        __syncthreads();
    }

    // ---- epilogue: bias + scale, write in MODE layout ----
    const int qrow = l >> 2;
    const int qcol = (l & 3) * 2;
#pragma unroll
    for (int i = 0; i < 2; i++) {
        const int r0 = m0 + wm + i * 16 + qrow;
#pragma unroll
        for (int j = 0; j < 8; j++) {
            const int n = n0 + wn + j * 8 + qcol;
            const float b0 = bias[n], b1 = bias[n + 1];
#pragma unroll
            for (int half = 0; half < 2; half++) {
                const int m = r0 + half * 8;
                const float v0 = (acc[i][j][half * 2 + 0] + b0) * scale;
                const float v1 = (acc[i][j][half * 2 + 1] + b1) * scale;
                if (MODE == 0) {
                    *(float2*)(C + (size_t)m * D_ + n) = make_float2(v0, v1);
                } else {
                    const int b = m >> 11;
                    const int t = m & (T_ - 1);
                    const int h = n >> 6;
                    const int d = n & (HD_ - 1);
                    *(float2*)(C + (((size_t)(b * H_ + h) * T_) + t) * HD_ + d) =
                        make_float2(v0, v1);
                }
            }
        }
    }
}

// ---------------------------------------------------------------------------
// Flash attention (unchanged): 1 thread = 1 query row, online softmax.
// ---------------------------------------------------------------------------
__global__ __launch_bounds__(128)
void attn_kernel(const float* __restrict__ Q,
                 const float* __restrict__ K,
                 const float* __restrict__ V,
                 const float* __restrict__ mask,
                 float* __restrict__ Ctx)
{
    __shared__ float Ks[64 * 64];
    __shared__ float Vs[64 * 64];

    const int tid = threadIdx.x;
    const int b = blockIdx.z;
    const int h = blockIdx.y;
    const int t = blockIdx.x * 128 + tid;

    const size_t head_base = (size_t)(b * H_ + h) * T_ * HD_;
    const float* qrow = Q + head_base + (size_t)t * HD_;

    float q[64], o[64];
#pragma unroll
    for (int i = 0; i < 16; i++) {
        const float4 v4 = ((const float4*)qrow)[i];
        q[4 * i + 0] = v4.x; q[4 * i + 1] = v4.y;
        q[4 * i + 2] = v4.z; q[4 * i + 3] = v4.w;
    }
#pragma unroll
    for (int d = 0; d < 64; d++) o[d] = 0.f;

    float m_i = -1e30f;
    float l   = 0.f;

    const float* maskrow = mask + ((size_t)b * T_ + t) * T_;
    const float* Kbase = K + head_base;
    const float* Vbase = V + head_base;

    for (int kt = 0; kt < T_ / 64; kt++) {
        const int j0 = kt * 64;
        __syncthreads();
        {
            const float4* ksrc = (const float4*)(Kbase + (size_t)j0 * HD_);
            const float4* vsrc = (const float4*)(Vbase + (size_t)j0 * HD_);
            float4* kdst = (float4*)Ks;
            float4* vdst = (float4*)Vs;
#pragma unroll
            for (int i = 0; i < 8; i++) {
                kdst[tid + i * 128] = ksrc[tid + i * 128];
                vdst[tid + i * 128] = vsrc[tid + i * 128];
            }
        }
        __syncthreads();

#pragma unroll 1
        for (int jj = 0; jj < 64; jj += 4) {
            const float4 mv = *(const float4*)(maskrow + j0 + jj);
            const float mk[4] = {mv.x, mv.y, mv.z, mv.w};
#pragma unroll
            for (int u = 0; u < 4; u++) {
                const int j = jj + u;
                const float4* kr = (const float4*)(Ks + j * 64);
                float s = mk[u];
#pragma unroll
                for (int d4 = 0; d4 < 16; d4++) {
                    const float4 kv = kr[d4];
                    s += q[4 * d4 + 0] * kv.x + q[4 * d4 + 1] * kv.y
                       + q[4 * d4 + 2] * kv.z + q[4 * d4 + 3] * kv.w;
                }
                float p;
                if (s > m_i) {
                    const float corr = __expf(m_i - s);
                    l *= corr;
#pragma unroll
                    for (int d = 0; d < 64; d++) o[d] *= corr;
                    m_i = s;
                    p = 1.f;
                } else {
                    p = __expf(s - m_i);
                }
                l += p;
                const float4* vr = (const float4*)(Vs + j * 64);
#pragma unroll
                for (int d4 = 0; d4 < 16; d4++) {
                    const float4 vv = vr[d4];
                    o[4 * d4 + 0] += p * vv.x;
                    o[4 * d4 + 1] += p * vv.y;
                    o[4 * d4 + 2] += p * vv.z;
                    o[4 * d4 + 3] += p * vv.w;
                }
            }
        }
    }

    const float inv = 1.f / l;
    float* orow = Ctx + ((size_t)b * T_ + t) * D_ + h * HD_;
#pragma unroll
    for (int i = 0; i < 16; i++) {
        ((float4*)orow)[i] = make_float4(o[4 * i + 0] * inv, o[4 * i + 1] * inv,
                                         o[4 * i + 2] * inv, o[4 * i + 3] * inv);
    }
}

// ---------------------------------------------------------------------------
// Launch
// ---------------------------------------------------------------------------
extern "C" void kernel_launch(void* const* d_in, const int* in_sizes, int n_in,
                              void* d_out, int out_size)
{
    const float* hs   = (const float*)d_in[0];
    const float* mask = (const float*)d_in[1];
    const float* Wq   = (const float*)d_in[2];
    const float* bq   = (const float*)d_in[3];
    const float* Wk   = (const float*)d_in[4];
    const float* bk   = (const float*)d_in[5];
    const float* Wv   = (const float*)d_in[6];
    const float* bv   = (const float*)d_in[7];
    const float* Wo   = (const float*)d_in[8];
    const float* bo   = (const float*)d_in[9];
    float* out = (float*)d_out;

    float *Qd, *Kd, *Vd, *Ctxd;
    cudaGetSymbolAddress((void**)&Qd,   g_Q);
    cudaGetSymbolAddress((void**)&Kd,   g_K);
    cudaGetSymbolAddress((void**)&Vd,   g_V);
    cudaGetSymbolAddress((void**)&Ctxd, g_Ctx);

    cudaFuncSetAttribute(gemm_mma<0>, cudaFuncAttributeMaxDynamicSharedMemorySize, GEMM_SMEM);
    cudaFuncSetAttribute(gemm_mma<1>, cudaFuncAttributeMaxDynamicSharedMemorySize, GEMM_SMEM);

    const dim3 gemmGrid(D_ / 128, M_ / 128);   // (8, 32)
    const float scaling = 0.125f;              // HD^-0.5

    gemm_mma<1><<<gemmGrid, 256, GEMM_SMEM>>>(hs, Wq, bq, Qd, scaling);
    gemm_mma<1><<<gemmGrid, 256, GEMM_SMEM>>>(hs, Wk, bk, Kd, 1.f);
    gemm_mma<1><<<gemmGrid, 256, GEMM_SMEM>>>(hs, Wv, bv, Vd, 1.f);

    attn_kernel<<<dim3(T_ / 128, H_, B_), 128>>>(Qd, Kd, Vd, mask, Ctxd);

    gemm_mma<0><<<gemmGrid, 256, GEMM_SMEM>>>(Ctxd, Wo, bo, out, 1.f);
}

// round 7
// speedup vs baseline: 3.4712x; 2.6267x over previous
#include <cuda_runtime.h>
#include <cuda_bf16.h>
#include <cuda_fp16.h>
#include <cstdint>

// Problem constants (MusicgenAttention: B=2, T=2048, D=1024, H=16, HD=64)
#define B_   2
#define T_   2048
#define D_   1024
#define H_   16
#define HD_  64
#define M_   (B_ * T_)

// Scratch (device globals — allocation-free per harness rules)
__device__ __half g_Qh[B_ * H_ * T_ * HD_];   // [B,H,T,HD] fp16 hi
__device__ __half g_Ql[B_ * H_ * T_ * HD_];   // fp16 lo residual
__device__ __half g_Kh[B_ * H_ * T_ * HD_];   // fp16
__device__ __half g_Vh[B_ * H_ * T_ * HD_];   // fp16
__device__ float  g_Ctx[B_ * T_ * D_];        // [B,T,D] fp32

// ---------------------------------------------------------------------------
// PTX helpers (base sm_80+ — this toolchain's ptxas targets plain sm_103,
// which rejects all tcgen05 'a'-features; legacy HMMA path it is)
// ---------------------------------------------------------------------------
__device__ __forceinline__ uint32_t smem_u32(const void* p) {
    uint32_t a;
    asm("{ .reg .u64 t; cvta.to.shared.u64 t, %1; cvt.u32.u64 %0, t; }" : "=r"(a) : "l"(p));
    return a;
}

#define LDMATRIX_X4(r, addr)                                                   \
    asm volatile("ldmatrix.sync.aligned.m8n8.x4.shared.b16 {%0,%1,%2,%3}, [%4];" \
        : "=r"((r)[0]), "=r"((r)[1]), "=r"((r)[2]), "=r"((r)[3]) : "r"(addr))

#define LDMATRIX_X4_T(r, addr)                                                 \
    asm volatile("ldmatrix.sync.aligned.m8n8.x4.trans.shared.b16 {%0,%1,%2,%3}, [%4];" \
        : "=r"((r)[0]), "=r"((r)[1]), "=r"((r)[2]), "=r"((r)[3]) : "r"(addr))

#define MMA_BF16(d, a, b0, b1)                                                 \
    asm volatile("mma.sync.aligned.m16n8k16.row.col.f32.bf16.bf16.f32 "        \
        "{%0,%1,%2,%3}, {%4,%5,%6,%7}, {%8,%9}, {%0,%1,%2,%3};"                \
        : "+f"((d)[0]), "+f"((d)[1]), "+f"((d)[2]), "+f"((d)[3])               \
        : "r"((a)[0]), "r"((a)[1]), "r"((a)[2]), "r"((a)[3]), "r"(b0), "r"(b1))

#define MMA_F16(d, a, b0, b1)                                                  \
    asm volatile("mma.sync.aligned.m16n8k16.row.col.f32.f16.f16.f32 "          \
        "{%0,%1,%2,%3}, {%4,%5,%6,%7}, {%8,%9}, {%0,%1,%2,%3};"                \
        : "+f"((d)[0]), "+f"((d)[1]), "+f"((d)[2]), "+f"((d)[3])               \
        : "r"((a)[0]), "r"((a)[1]), "r"((a)[2]), "r"((a)[3]), "r"(b0), "r"(b1))

__device__ __forceinline__ void cp_async16(uint32_t dst, const void* src) {
    asm volatile("cp.async.cg.shared.global [%0], [%1], 16;" :: "r"(dst), "l"(src));
}
#define CP_COMMIT() asm volatile("cp.async.commit_group;" ::: "memory")
#define CP_WAIT(n)  asm volatile("cp.async.wait_group %0;" :: "n"(n) : "memory")

// ---------------------------------------------------------------------------
// Projection GEMM (validated R4): C = (A @ W^T + bias) * scale via 3-term
// bf16 split on tensor cores. Epilogue MODEs:
//   0: fp32 C0[m*D+n]
//   1: fp16 split -> Ch/Cl at [B,H,T,HD]
//   2: fp16 single -> Ch at [B,H,T,HD]
// ---------------------------------------------------------------------------
#define BK 32
#define NITER (D_ / BK)
#define TILE_B  (128 * BK * 2)
#define STAGE_B (4 * TILE_B)
#define GEMM_SMEM (2 * STAGE_B)

__device__ __forceinline__ uint32_t swz(int r, int c) {        // 64B rows
    return (uint32_t)(r * 64 + ((c ^ ((r >> 1) & 3)) << 4));
}
__device__ __forceinline__ uint32_t swz128(int r, int c) {     // 128B rows
    return (uint32_t)(r * 128 + ((c ^ (r & 7)) << 4));
}

__device__ __forceinline__ void cvt_split8(const float* f, uint4& hi, uint4& lo) {
    uint32_t h[4], l[4];
#pragma unroll
    for (int i = 0; i < 4; i++) {
        __nv_bfloat162 hb = __float22bfloat162_rn(make_float2(f[2 * i], f[2 * i + 1]));
        float2 hf = __bfloat1622float2(hb);
        __nv_bfloat162 lb = __float22bfloat162_rn(
            make_float2(f[2 * i] - hf.x, f[2 * i + 1] - hf.y));
        h[i] = *(uint32_t*)&hb;
        l[i] = *(uint32_t*)&lb;
    }
    hi = make_uint4(h[0], h[1], h[2], h[3]);
    lo = make_uint4(l[0], l[1], l[2], l[3]);
}

template <int MODE>
__global__ __launch_bounds__(256)
void gemm_mma(const float* __restrict__ A, const float* __restrict__ W,
              const float* __restrict__ bias, float* __restrict__ C0,
              __half* __restrict__ Ch, __half* __restrict__ Cl, float scale)
{
    extern __shared__ char smem[];
    const uint32_t sbase = smem_u32(smem);

    const int tid = threadIdx.x;
    const int wid = tid >> 5;
    const int l   = tid & 31;
    const int m0 = blockIdx.y * 128;
    const int n0 = blockIdx.x * 128;
    const int wm = (wid >> 1) * 32;
    const int wn = (wid & 1) * 64;

    float acc[2][8][4];
#pragma unroll
    for (int i = 0; i < 2; i++)
#pragma unroll
        for (int j = 0; j < 8; j++)
#pragma unroll
            for (int c = 0; c < 4; c++) acc[i][j][c] = 0.f;

    const int ch0 = tid * 2;
    const int lr  = ch0 >> 2;
    const int lc0 = ch0 & 3;

    float abuf[16], wbuf[16];
    {
        const float* Ar = A + (size_t)(m0 + lr) * D_ + lc0 * 8;
        const float* Wr = W + (size_t)(n0 + lr) * D_ + lc0 * 8;
#pragma unroll
        for (int u = 0; u < 4; u++) {
            *(float4*)(abuf + u * 4) = *(const float4*)(Ar + u * 4);
            *(float4*)(wbuf + u * 4) = *(const float4*)(Wr + u * 4);
        }
    }

    for (int it = 0; it < NITER; it++) {
        const int s = it & 1;
        const uint32_t stage = sbase + s * STAGE_B;
        {
            char* st = smem + s * STAGE_B;
#pragma unroll
            for (int u = 0; u < 2; u++) {
                const uint32_t sw = swz(lr, lc0 + u);
                uint4 hi, lo;
                cvt_split8(abuf + u * 8, hi, lo);
                *(uint4*)(st + sw)          = hi;
                *(uint4*)(st + TILE_B + sw) = lo;
                cvt_split8(wbuf + u * 8, hi, lo);
                *(uint4*)(st + 2 * TILE_B + sw) = hi;
                *(uint4*)(st + 3 * TILE_B + sw) = lo;
            }
        }
        __syncthreads();

        if (it + 1 < NITER) {
            const int k0 = (it + 1) * BK;
            const float* Ar = A + (size_t)(m0 + lr) * D_ + k0 + lc0 * 8;
            const float* Wr = W + (size_t)(n0 + lr) * D_ + k0 + lc0 * 8;
#pragma unroll
            for (int u = 0; u < 4; u++) {
                *(float4*)(abuf + u * 4) = *(const float4*)(Ar + u * 4);
                *(float4*)(wbuf + u * 4) = *(const float4*)(Wr + u * 4);
            }
        }

        const uint32_t AhU = stage;
        const uint32_t AlU = stage + TILE_B;
        const uint32_t WhU = stage + 2 * TILE_B;
        const uint32_t WlU = stage + 3 * TILE_B;

#pragma unroll
        for (int ks = 0; ks < 2; ks++) {
            const int c0 = ks * 2;
            uint32_t afh[2][4], afl[2][4];
            {
                const int rA = wm + (l & 7) + ((l >> 3) & 1) * 8;
                const int cA = c0 + (l >> 4);
#pragma unroll
                for (int i = 0; i < 2; i++) {
                    const uint32_t off = swz(rA + i * 16, cA);
                    LDMATRIX_X4(afh[i], AhU + off);
                    LDMATRIX_X4(afl[i], AlU + off);
                }
            }
#pragma unroll
            for (int jp = 0; jp < 4; jp++) {
                const int rB = wn + jp * 16 + (l & 7) + ((l >> 4) & 1) * 8;
                const int cB = c0 + ((l >> 3) & 1);
                const uint32_t off = swz(rB, cB);
                uint32_t bh[4], bl[4];
                LDMATRIX_X4(bh, WhU + off);
                LDMATRIX_X4(bl, WlU + off);
#pragma unroll
                for (int i = 0; i < 2; i++) {
                    MMA_BF16(acc[i][jp * 2],     afh[i], bh[0], bh[1]);
                    MMA_BF16(acc[i][jp * 2],     afl[i], bh[0], bh[1]);
                    MMA_BF16(acc[i][jp * 2],     afh[i], bl[0], bl[1]);
                    MMA_BF16(acc[i][jp * 2 + 1], afh[i], bh[2], bh[3]);
                    MMA_BF16(acc[i][jp * 2 + 1], afl[i], bh[2], bh[3]);
                    MMA_BF16(acc[i][jp * 2 + 1], afh[i], bl[2], bl[3]);
                }
            }
        }
        __syncthreads();
    }

    const int qrow = l >> 2;
    const int qcol = (l & 3) * 2;
#pragma unroll
    for (int i = 0; i < 2; i++) {
        const int r0 = m0 + wm + i * 16 + qrow;
#pragma unroll
        for (int j = 0; j < 8; j++) {
            const int n = n0 + wn + j * 8 + qcol;
            const float b0 = bias[n], b1 = bias[n + 1];
#pragma unroll
            for (int half = 0; half < 2; half++) {
                const int m = r0 + half * 8;
                const float v0 = (acc[i][j][half * 2 + 0] + b0) * scale;
                const float v1 = (acc[i][j][half * 2 + 1] + b1) * scale;
                if (MODE == 0) {
                    *(float2*)(C0 + (size_t)m * D_ + n) = make_float2(v0, v1);
                } else {
                    const int b = m >> 11;
                    const int t = m & (T_ - 1);
                    const int h = n >> 6;
                    const int d = n & (HD_ - 1);
                    const size_t idx = (((size_t)(b * H_ + h) * T_) + t) * HD_ + d;
                    const __half h0 = __float2half_rn(v0);
                    const __half h1 = __float2half_rn(v1);
                    *(__half2*)(Ch + idx) = __halves2half2(h0, h1);
                    if (MODE == 1) {
                        const __half l0v = __float2half_rn(v0 - __half2float(h0));
                        const __half l1v = __float2half_rn(v1 - __half2float(h1));
                        *(__half2*)(Cl + idx) = __halves2half2(l0v, l1v);
                    }
                }
            }
        }
    }
}

// ---------------------------------------------------------------------------
// Tensor-core flash attention.
// Grid (16,16,2), 256 threads (8 warps x 16 query rows). KC=64 keys/chunk.
// s = QhKh + QlKh (fp16, fp32 accum); online softmax; o += P_f16 @ V_f16.
// ---------------------------------------------------------------------------
#define ATTN_SMEM 65536   // Qh(16K) Ql(16K) + 2 KV stages of (Kh 8K + Vh 8K)

__global__ __launch_bounds__(256)
void attn_mma(const __half* __restrict__ Qh, const __half* __restrict__ Ql,
              const __half* __restrict__ Kh, const __half* __restrict__ Vh,
              const float* __restrict__ mask, float* __restrict__ Ctx)
{
    extern __shared__ char smem[];
    const uint32_t sb = smem_u32(smem);
    const int tid = threadIdx.x;
    const int wid = tid >> 5;
    const int l   = tid & 31;
    const int lq  = l & 3;
    const int b = blockIdx.z, h = blockIdx.y;
    const int q0 = blockIdx.x * 128;
    const size_t hb = (size_t)(b * H_ + h) * T_ * HD_;

    const uint32_t QHs = sb, QLs = sb + 16384, KV = sb + 32768;

    // Q tiles -> smem (fp16, 128B rows)
#pragma unroll
    for (int i = 0; i < 8; i++) {
        const int idx = tid + i * 256;
        const int tile = idx >> 10, r = (idx >> 3) & 127, c = idx & 7;
        const __half* src = (tile ? Ql : Qh) + hb + (size_t)(q0 + r) * HD_ + c * 8;
        cp_async16((tile ? QLs : QHs) + swz128(r, c), src);
    }
    CP_COMMIT();
    // KV chunk 0
#pragma unroll
    for (int i = 0; i < 4; i++) {
        const int idx = tid + i * 256;
        const int tile = idx >> 9, r = (idx >> 3) & 63, c = idx & 7;
        const __half* src = (tile ? Vh : Kh) + hb + (size_t)r * HD_ + c * 8;
        cp_async16(KV + tile * 8192 + swz128(r, c), src);
    }
    CP_COMMIT();

    CP_WAIT(1);            // Q resident (KV0 may still be in flight)
    __syncthreads();

    // Q fragments, kept in registers for the whole kernel
    uint32_t aqh[4][4], aql[4][4];
    {
        const int rA = wid * 16 + (l & 15);
#pragma unroll
        for (int kc = 0; kc < 4; kc++) {
            const int cA = 2 * kc + (l >> 4);
            LDMATRIX_X4(aqh[kc], QHs + swz128(rA, cA));
            LDMATRIX_X4(aql[kc], QLs + swz128(rA, cA));
        }
    }

    float oacc[8][4];
#pragma unroll
    for (int j = 0; j < 8; j++)
#pragma unroll
        for (int e = 0; e < 4; e++) oacc[j][e] = 0.f;
    float m0 = -1e30f, m1 = -1e30f, l0 = 0.f, l1 = 0.f;

    const float* mr0 = mask + ((size_t)b * T_ + q0 + wid * 16 + (l >> 2)) * T_;
    const float* mr1 = mr0 + 8 * T_;

    const int rBk = (l & 7) + ((l >> 4) & 1) * 8;   // K-frag row-in-pair
    const int cBo = (l >> 3) & 1;                    // K-frag chunk parity
    const int rVt = (l & 7) + ((l >> 3) & 1) * 8;    // V-frag (trans) row
    const int cVo = l >> 4;                          // V-frag chunk parity

    for (int kt = 0; kt < 32; kt++) {
        const int s = kt & 1;
        if (kt + 1 < 32) {
#pragma unroll
            for (int i = 0; i < 4; i++) {
                const int idx = tid + i * 256;
                const int tile = idx >> 9, r = (idx >> 3) & 63, c = idx & 7;
                const __half* src = (tile ? Vh : Kh) + hb +
                                    (size_t)((kt + 1) * 64 + r) * HD_ + c * 8;
                cp_async16(KV + (s ^ 1) * 16384 + tile * 8192 + swz128(r, c), src);
            }
            CP_COMMIT();
            CP_WAIT(1);
        } else {
            CP_WAIT(0);
        }
        __syncthreads();

        const uint32_t KHs = KV + s * 16384;
        const uint32_t VHs = KHs + 8192;

        // ---- S = Q K^T (2-term fp16) ----
        float sacc[8][4];
#pragma unroll
        for (int j = 0; j < 8; j++)
#pragma unroll
            for (int e = 0; e < 4; e++) sacc[j][e] = 0.f;

#pragma unroll
        for (int kc = 0; kc < 4; kc++) {
#pragma unroll
            for (int jp = 0; jp < 4; jp++) {
                uint32_t kb[4];
                LDMATRIX_X4(kb, KHs + swz128(jp * 16 + rBk, 2 * kc + cBo));
                MMA_F16(sacc[jp * 2],     aqh[kc], kb[0], kb[1]);
                MMA_F16(sacc[jp * 2],     aql[kc], kb[0], kb[1]);
                MMA_F16(sacc[jp * 2 + 1], aqh[kc], kb[2], kb[3]);
                MMA_F16(sacc[jp * 2 + 1], aql[kc], kb[2], kb[3]);
            }
        }

        // ---- +mask ----
        const int mb = kt * 64 + 2 * lq;
#pragma unroll
        for (int j = 0; j < 8; j++) {
            const float2 u0 = *(const float2*)(mr0 + mb + j * 8);
            const float2 u1 = *(const float2*)(mr1 + mb + j * 8);
            sacc[j][0] += u0.x; sacc[j][1] += u0.y;
            sacc[j][2] += u1.x; sacc[j][3] += u1.y;
        }

        // ---- online softmax (rows r, r+8 per thread quad) ----
        float mx0 = -1e30f, mx1 = -1e30f;
#pragma unroll
        for (int j = 0; j < 8; j++) {
            mx0 = fmaxf(mx0, fmaxf(sacc[j][0], sacc[j][1]));
            mx1 = fmaxf(mx1, fmaxf(sacc[j][2], sacc[j][3]));
        }
        mx0 = fmaxf(mx0, __shfl_xor_sync(0xffffffffu, mx0, 1));
        mx0 = fmaxf(mx0, __shfl_xor_sync(0xffffffffu, mx0, 2));
        mx1 = fmaxf(mx1, __shfl_xor_sync(0xffffffffu, mx1, 1));
        mx1 = fmaxf(mx1, __shfl_xor_sync(0xffffffffu, mx1, 2));

        const float mn0 = fmaxf(m0, mx0);
        const float mn1 = fmaxf(m1, mx1);
        const float cr0 = __expf(m0 - mn0);
        const float cr1 = __expf(m1 - mn1);
        m0 = mn0; m1 = mn1;

        float rs0 = 0.f, rs1 = 0.f;
#pragma unroll
        for (int j = 0; j < 8; j++) {
            sacc[j][0] = __expf(sacc[j][0] - mn0);
            sacc[j][1] = __expf(sacc[j][1] - mn0);
            sacc[j][2] = __expf(sacc[j][2] - mn1);
            sacc[j][3] = __expf(sacc[j][3] - mn1);
            rs0 += sacc[j][0] + sacc[j][1];
            rs1 += sacc[j][2] + sacc[j][3];
        }
        rs0 += __shfl_xor_sync(0xffffffffu, rs0, 1);
        rs0 += __shfl_xor_sync(0xffffffffu, rs0, 2);
        rs1 += __shfl_xor_sync(0xffffffffu, rs1, 1);
        rs1 += __shfl_xor_sync(0xffffffffu, rs1, 2);
        l0 = l0 * cr0 + rs0;
        l1 = l1 * cr1 + rs1;

#pragma unroll
        for (int j = 0; j < 8; j++) {
            oacc[j][0] *= cr0; oacc[j][1] *= cr0;
            oacc[j][2] *= cr1; oacc[j][3] *= cr1;
        }

        // ---- o += P @ V (fp16 P, fp16 V) ----
#pragma unroll
        for (int kc = 0; kc < 4; kc++) {
            uint32_t pa[4];
            {
                __half2 p0 = __floats2half2_rn(sacc[2 * kc][0], sacc[2 * kc][1]);
                __half2 p1 = __floats2half2_rn(sacc[2 * kc][2], sacc[2 * kc][3]);
                __half2 p2 = __floats2half2_rn(sacc[2 * kc + 1][0], sacc[2 * kc + 1][1]);
                __half2 p3 = __floats2half2_rn(sacc[2 * kc + 1][2], sacc[2 * kc + 1][3]);
                pa[0] = *(uint32_t*)&p0; pa[1] = *(uint32_t*)&p1;
                pa[2] = *(uint32_t*)&p2; pa[3] = *(uint32_t*)&p3;
            }
#pragma unroll
            for (int dp = 0; dp < 4; dp++) {
                uint32_t vb[4];
                LDMATRIX_X4_T(vb, VHs + swz128(kc * 16 + rVt, 2 * dp + cVo));
                MMA_F16(oacc[dp * 2],     pa, vb[0], vb[1]);
                MMA_F16(oacc[dp * 2 + 1], pa, vb[2], vb[3]);
            }
        }
        __syncthreads();
    }

    // ---- epilogue: o / l -> Ctx [B,T,D] ----
    const float i0 = 1.f / l0;
    const float i1 = 1.f / l1;
    float* orow0 = Ctx + ((size_t)b * T_ + q0 + wid * 16 + (l >> 2)) * D_ + h * HD_;
    float* orow1 = orow0 + 8 * D_;
#pragma unroll
    for (int j = 0; j < 8; j++) {
        *(float2*)(orow0 + j * 8 + 2 * lq) =
            make_float2(oacc[j][0] * i0, oacc[j][1] * i0);
        *(float2*)(orow1 + j * 8 + 2 * lq) =
            make_float2(oacc[j][2] * i1, oacc[j][3] * i1);
    }
}

// ---------------------------------------------------------------------------
// Launch
// ---------------------------------------------------------------------------
extern "C" void kernel_launch(void* const* d_in, const int* in_sizes, int n_in,
                              void* d_out, int out_size)
{
    const float* hs   = (const float*)d_in[0];
    const float* mask = (const float*)d_in[1];
    const float* Wq   = (const float*)d_in[2];
    const float* bq   = (const float*)d_in[3];
    const float* Wk   = (const float*)d_in[4];
    const float* bk   = (const float*)d_in[5];
    const float* Wv   = (const float*)d_in[6];
    const float* bv   = (const float*)d_in[7];
    const float* Wo   = (const float*)d_in[8];
    const float* bo   = (const float*)d_in[9];
    float* out = (float*)d_out;

    __half *Qhd, *Qld, *Khd, *Vhd;
    float *Ctxd;
    cudaGetSymbolAddress((void**)&Qhd, g_Qh);
    cudaGetSymbolAddress((void**)&Qld, g_Ql);
    cudaGetSymbolAddress((void**)&Khd, g_Kh);
    cudaGetSymbolAddress((void**)&Vhd, g_Vh);
    cudaGetSymbolAddress((void**)&Ctxd, g_Ctx);

    cudaFuncSetAttribute(gemm_mma<0>, cudaFuncAttributeMaxDynamicSharedMemorySize, GEMM_SMEM);
    cudaFuncSetAttribute(gemm_mma<1>, cudaFuncAttributeMaxDynamicSharedMemorySize, GEMM_SMEM);
    cudaFuncSetAttribute(gemm_mma<2>, cudaFuncAttributeMaxDynamicSharedMemorySize, GEMM_SMEM);
    cudaFuncSetAttribute(attn_mma, cudaFuncAttributeMaxDynamicSharedMemorySize, ATTN_SMEM);

    const dim3 gemmGrid(D_ / 128, M_ / 128);
    const float scaling = 0.125f;   // HD^-0.5

    gemm_mma<1><<<gemmGrid, 256, GEMM_SMEM>>>(hs, Wq, bq, nullptr, Qhd, Qld, scaling);
    gemm_mma<2><<<gemmGrid, 256, GEMM_SMEM>>>(hs, Wk, bk, nullptr, Khd, nullptr, 1.f);
    gemm_mma<2><<<gemmGrid, 256, GEMM_SMEM>>>(hs, Wv, bv, nullptr, Vhd, nullptr, 1.f);

    attn_mma<<<dim3(T_ / 128, H_, B_), 256, ATTN_SMEM>>>(Qhd, Qld, Khd, Vhd, mask, Ctxd);

    gemm_mma<0><<<gemmGrid, 256, GEMM_SMEM>>>(Ctxd, Wo, bo, out, nullptr, nullptr, 1.f);
}

// round 11
// speedup vs baseline: 7.5708x; 2.1811x over previous
#include <cuda_runtime.h>
#include <cuda_fp16.h>
#include <cstdint>

// Problem constants (MusicgenAttention: B=2, T=2048, D=1024, H=16, HD=64)
#define B_   2
#define T_   2048
#define D_   1024
#define H_   16
#define HD_  64
#define M_   (B_ * T_)

// Scratch (device globals — allocation-free per harness rules)
__device__ __half g_HSh[M_ * D_];            // hidden_states fp16
__device__ __half g_Wqh[D_ * D_];
__device__ __half g_Wkh[D_ * D_];
__device__ __half g_Wvh[D_ * D_];
__device__ __half g_Woh[D_ * D_];
__device__ __half g_Qh[B_ * H_ * T_ * HD_];  // [B,H,T,HD]
__device__ __half g_Kh[B_ * H_ * T_ * HD_];
__device__ __half g_Vh[B_ * H_ * T_ * HD_];
__device__ __half g_Ctx[M_ * D_];            // [B,T,D] fp16

// ---------------------------------------------------------------------------
// PTX helpers (base sm_80+ — this toolchain's ptxas targets plain sm_103,
// which rejects tcgen05 'a'-features; legacy HMMA path)
// ---------------------------------------------------------------------------
__device__ __forceinline__ uint32_t smem_u32(const void* p) {
    uint32_t a;
    asm("{ .reg .u64 t; cvta.to.shared.u64 t, %1; cvt.u32.u64 %0, t; }" : "=r"(a) : "l"(p));
    return a;
}

#define LDMATRIX_X4(r, addr)                                                   \
    asm volatile("ldmatrix.sync.aligned.m8n8.x4.shared.b16 {%0,%1,%2,%3}, [%4];" \
        : "=r"((r)[0]), "=r"((r)[1]), "=r"((r)[2]), "=r"((r)[3]) : "r"(addr))

#define LDMATRIX_X4_T(r, addr)                                                 \
    asm volatile("ldmatrix.sync.aligned.m8n8.x4.trans.shared.b16 {%0,%1,%2,%3}, [%4];" \
        : "=r"((r)[0]), "=r"((r)[1]), "=r"((r)[2]), "=r"((r)[3]) : "r"(addr))

#define MMA_F16(d, a, b0, b1)                                                  \
    asm volatile("mma.sync.aligned.m16n8k16.row.col.f32.f16.f16.f32 "          \
        "{%0,%1,%2,%3}, {%4,%5,%6,%7}, {%8,%9}, {%0,%1,%2,%3};"                \
        : "+f"((d)[0]), "+f"((d)[1]), "+f"((d)[2]), "+f"((d)[3])               \
        : "r"((a)[0]), "r"((a)[1]), "r"((a)[2]), "r"((a)[3]), "r"(b0), "r"(b1))

__device__ __forceinline__ void cp_async16(uint32_t dst, const void* src) {
    asm volatile("cp.async.cg.shared.global [%0], [%1], 16;" :: "r"(dst), "l"(src));
}
#define CP_COMMIT() asm volatile("cp.async.commit_group;" ::: "memory")
#define CP_WAIT(n)  asm volatile("cp.async.wait_group %0;" :: "n"(n) : "memory")

__device__ __forceinline__ uint32_t swz128(int r, int c) {   // 128B rows
    return (uint32_t)(r * 128 + ((c ^ (r & 7)) << 4));
}

// ---------------------------------------------------------------------------
// fp32 -> fp16 bulk convert (8 elems/thread)
// ---------------------------------------------------------------------------
__global__ __launch_bounds__(256)
void f32_to_f16(const float* __restrict__ in, __half* __restrict__ out, int n8)
{
    const int i = blockIdx.x * 256 + threadIdx.x;
    if (i < n8) {
        const float4 v0 = ((const float4*)in)[2 * i];
        const float4 v1 = ((const float4*)in)[2 * i + 1];
        __half2 h0 = __floats2half2_rn(v0.x, v0.y);
        __half2 h1 = __floats2half2_rn(v0.z, v0.w);
        __half2 h2 = __floats2half2_rn(v1.x, v1.y);
        __half2 h3 = __floats2half2_rn(v1.z, v1.w);
        ((uint4*)out)[i] = make_uint4(*(uint32_t*)&h0, *(uint32_t*)&h1,
                                      *(uint32_t*)&h2, *(uint32_t*)&h3);
    }
}

// ---------------------------------------------------------------------------
// 1-term fp16 GEMM: C = (A @ W^T + bias) * scale
//   A: [rows,1024] fp16 row-major; W: [1024,1024] fp16 row-major
// Tile 128x128, BK=64, 2-stage cp.async pipeline, 256 threads, 2 CTAs/SM.
//   MODE 0: fp32 C0[m*D+n];  MODE 1: fp16 Ch at [B,H,T,HD]
// ---------------------------------------------------------------------------
#define GBK 64
#define GNIT (D_ / GBK)                 // 16
#define GTILE_B (128 * GBK * 2)         // 16384 per operand tile
#define GSTAGE_B (2 * GTILE_B)          // 32768
#define GEMM_SMEM (2 * GSTAGE_B)        // 65536

template <int MODE>
__global__ __launch_bounds__(256, 2)
void gemm_f16(const __half* __restrict__ A, const __half* __restrict__ W,
              const float* __restrict__ bias, float* __restrict__ C0,
              __half* __restrict__ Ch, float scale)
{
    extern __shared__ char smem[];
    const uint32_t sbase = smem_u32(smem);

    const int tid = threadIdx.x;
    const int wid = tid >> 5;
    const int l   = tid & 31;
    const int m0 = blockIdx.y * 128;
    const int n0 = blockIdx.x * 128;
    const int wm = (wid >> 1) * 32;
    const int wn = (wid & 1) * 64;

    float acc[2][8][4];
#pragma unroll
    for (int i = 0; i < 2; i++)
#pragma unroll
        for (int j = 0; j < 8; j++)
#pragma unroll
            for (int c = 0; c < 4; c++) acc[i][j][c] = 0.f;

    // stage loader: A tile (128x64) + W tile (128x64), 2048 x 16B chunks
#define GLOAD(it, s) do {                                                      \
        const uint32_t st = sbase + (s) * GSTAGE_B;                            \
        const int k0 = (it) * GBK;                                             \
        _Pragma("unroll")                                                      \
        for (int i = 0; i < 8; i++) {                                          \
            const int idx = tid + i * 256;                                     \
            const int tile = idx >> 10;                                        \
            const int r = (idx >> 3) & 127;                                    \
            const int c = idx & 7;                                             \
            const __half* src = (tile ? W + (size_t)(n0 + r) * D_              \
                                      : A + (size_t)(m0 + r) * D_) + k0 + c * 8; \
            cp_async16(st + tile * GTILE_B + swz128(r, c), src);               \
        }                                                                      \
    } while (0)

    GLOAD(0, 0); CP_COMMIT();

    for (int it = 0; it < GNIT; it++) {
        const int s = it & 1;
        CP_WAIT(0);
        __syncthreads();
        if (it + 1 < GNIT) { GLOAD(it + 1, s ^ 1); CP_COMMIT(); }

        const uint32_t As = sbase + s * GSTAGE_B;
        const uint32_t Ws = As + GTILE_B;

#pragma unroll
        for (int kc = 0; kc < 4; kc++) {
            uint32_t af[2][4];
            const int rA = wm + (l & 15);
            const int cA = 2 * kc + (l >> 4);
            LDMATRIX_X4(af[0], As + swz128(rA, cA));
            LDMATRIX_X4(af[1], As + swz128(rA + 16, cA));
#pragma unroll
            for (int jp = 0; jp < 4; jp++) {
                const int rB = wn + jp * 16 + (l & 7) + ((l >> 4) & 1) * 8;
                const int cB = 2 * kc + ((l >> 3) & 1);
                uint32_t bf[4];
                LDMATRIX_X4(bf, Ws + swz128(rB, cB));
                MMA_F16(acc[0][jp * 2],     af[0], bf[0], bf[1]);
                MMA_F16(acc[0][jp * 2 + 1], af[0], bf[2], bf[3]);
                MMA_F16(acc[1][jp * 2],     af[1], bf[0], bf[1]);
                MMA_F16(acc[1][jp * 2 + 1], af[1], bf[2], bf[3]);
            }
        }
    }

    // epilogue
    const int qrow = l >> 2;
    const int qcol = (l & 3) * 2;
#pragma unroll
    for (int i = 0; i < 2; i++) {
        const int r0 = m0 + wm + i * 16 + qrow;
#pragma unroll
        for (int j = 0; j < 8; j++) {
            const int n = n0 + wn + j * 8 + qcol;
            const float b0 = bias[n], b1 = bias[n + 1];
#pragma unroll
            for (int half = 0; half < 2; half++) {
                const int m = r0 + half * 8;
                const float v0 = (acc[i][j][half * 2 + 0] + b0) * scale;
                const float v1 = (acc[i][j][half * 2 + 1] + b1) * scale;
                if (MODE == 0) {
                    *(float2*)(C0 + (size_t)m * D_ + n) = make_float2(v0, v1);
                } else {
                    const int b = m >> 11;
                    const int t = m & (T_ - 1);
                    const int h = n >> 6;
                    const int d = n & (HD_ - 1);
                    __half2 hv = __floats2half2_rn(v0, v1);
                    *(__half2*)(Ch + (((size_t)(b * H_ + h) * T_) + t) * HD_ + d) = hv;
                }
            }
        }
    }
}

// ---------------------------------------------------------------------------
// Tensor-core flash attention (1-term fp16 QK).
// Grid (16,16,2), 256 threads (8 warps x 16 query rows), KC=64 keys/chunk.
// Writes Ctx as fp16 [B,T,D].
// ---------------------------------------------------------------------------
#define ATTN_SMEM 49152   // Q 16K + 2 KV stages of (K 8K + V 8K)

__global__ __launch_bounds__(256, 2)
void attn_mma(const __half* __restrict__ Qh, const __half* __restrict__ Kh,
              const __half* __restrict__ Vh, const float* __restrict__ mask,
              __half* __restrict__ Ctx)
{
    extern __shared__ char smem[];
    const uint32_t sb = smem_u32(smem);
    const int tid = threadIdx.x;
    const int wid = tid >> 5;
    const int l   = tid & 31;
    const int lq  = l & 3;
    const int b = blockIdx.z, h = blockIdx.y;
    const int q0 = blockIdx.x * 128;
    const size_t hb = (size_t)(b * H_ + h) * T_ * HD_;

    const uint32_t QHs = sb, KV = sb + 16384;

    // Q tile -> smem
#pragma unroll
    for (int i = 0; i < 4; i++) {
        const int idx = tid + i * 256;
        const int r = idx >> 3, c = idx & 7;
        cp_async16(QHs + swz128(r, c), Qh + hb + (size_t)(q0 + r) * HD_ + c * 8);
    }
    CP_COMMIT();
    // KV chunk 0
#pragma unroll
    for (int i = 0; i < 4; i++) {
        const int idx = tid + i * 256;
        const int tile = idx >> 9, r = (idx >> 3) & 63, c = idx & 7;
        const __half* src = (tile ? Vh : Kh) + hb + (size_t)r * HD_ + c * 8;
        cp_async16(KV + tile * 8192 + swz128(r, c), src);
    }
    CP_COMMIT();

    CP_WAIT(1);
    __syncthreads();

    uint32_t aq[4][4];
    {
        const int rA = wid * 16 + (l & 15);
#pragma unroll
        for (int kc = 0; kc < 4; kc++)
            LDMATRIX_X4(aq[kc], QHs + swz128(rA, 2 * kc + (l >> 4)));
    }

    float oacc[8][4];
#pragma unroll
    for (int j = 0; j < 8; j++)
#pragma unroll
        for (int e = 0; e < 4; e++) oacc[j][e] = 0.f;
    float m0 = -1e30f, m1 = -1e30f, l0 = 0.f, l1 = 0.f;

    const float* mr0 = mask + ((size_t)b * T_ + q0 + wid * 16 + (l >> 2)) * T_;
    const float* mr1 = mr0 + 8 * T_;

    const int rBk = (l & 7) + ((l >> 4) & 1) * 8;
    const int cBo = (l >> 3) & 1;
    const int rVt = (l & 7) + ((l >> 3) & 1) * 8;
    const int cVo = l >> 4;

    for (int kt = 0; kt < 32; kt++) {
        const int s = kt & 1;
        if (kt + 1 < 32) {
#pragma unroll
            for (int i = 0; i < 4; i++) {
                const int idx = tid + i * 256;
                const int tile = idx >> 9, r = (idx >> 3) & 63, c = idx & 7;
                const __half* src = (tile ? Vh : Kh) + hb +
                                    (size_t)((kt + 1) * 64 + r) * HD_ + c * 8;
                cp_async16(KV + (s ^ 1) * 16384 + tile * 8192 + swz128(r, c), src);
            }
            CP_COMMIT();
            CP_WAIT(1);
        } else {
            CP_WAIT(0);
        }
        __syncthreads();

        const uint32_t KHs = KV + s * 16384;
        const uint32_t VHs = KHs + 8192;

        // ---- S = Q K^T ----
        float sacc[8][4];
#pragma unroll
        for (int j = 0; j < 8; j++)
#pragma unroll
            for (int e = 0; e < 4; e++) sacc[j][e] = 0.f;

#pragma unroll
        for (int kc = 0; kc < 4; kc++) {
#pragma unroll
            for (int jp = 0; jp < 4; jp++) {
                uint32_t kb[4];
                LDMATRIX_X4(kb, KHs + swz128(jp * 16 + rBk, 2 * kc + cBo));
                MMA_F16(sacc[jp * 2],     aq[kc], kb[0], kb[1]);
                MMA_F16(sacc[jp * 2 + 1], aq[kc], kb[2], kb[3]);
            }
        }

        // ---- +mask ----
        const int mb = kt * 64 + 2 * lq;
#pragma unroll
        for (int j = 0; j < 8; j++) {
            const float2 u0 = *(const float2*)(mr0 + mb + j * 8);
            const float2 u1 = *(const float2*)(mr1 + mb + j * 8);
            sacc[j][0] += u0.x; sacc[j][1] += u0.y;
            sacc[j][2] += u1.x; sacc[j][3] += u1.y;
        }

        // ---- online softmax ----
        float mx0 = -1e30f, mx1 = -1e30f;
#pragma unroll
        for (int j = 0; j < 8; j++) {
            mx0 = fmaxf(mx0, fmaxf(sacc[j][0], sacc[j][1]));
            mx1 = fmaxf(mx1, fmaxf(sacc[j][2], sacc[j][3]));
        }
        mx0 = fmaxf(mx0, __shfl_xor_sync(0xffffffffu, mx0, 1));
        mx0 = fmaxf(mx0, __shfl_xor_sync(0xffffffffu, mx0, 2));
        mx1 = fmaxf(mx1, __shfl_xor_sync(0xffffffffu, mx1, 1));
        mx1 = fmaxf(mx1, __shfl_xor_sync(0xffffffffu, mx1, 2));

        const float mn0 = fmaxf(m0, mx0);
        const float mn1 = fmaxf(m1, mx1);
        const float cr0 = __expf(m0 - mn0);
        const float cr1 = __expf(m1 - mn1);
        m0 = mn0; m1 = mn1;

        float rs0 = 0.f, rs1 = 0.f;
#pragma unroll
        for (int j = 0; j < 8; j++) {
            sacc[j][0] = __expf(sacc[j][0] - mn0);
            sacc[j][1] = __expf(sacc[j][1] - mn0);
            sacc[j][2] = __expf(sacc[j][2] - mn1);
            sacc[j][3] = __expf(sacc[j][3] - mn1);
            rs0 += sacc[j][0] + sacc[j][1];
            rs1 += sacc[j][2] + sacc[j][3];
        }
        rs0 += __shfl_xor_sync(0xffffffffu, rs0, 1);
        rs0 += __shfl_xor_sync(0xffffffffu, rs0, 2);
        rs1 += __shfl_xor_sync(0xffffffffu, rs1, 1);
        rs1 += __shfl_xor_sync(0xffffffffu, rs1, 2);
        l0 = l0 * cr0 + rs0;
        l1 = l1 * cr1 + rs1;

#pragma unroll
        for (int j = 0; j < 8; j++) {
            oacc[j][0] *= cr0; oacc[j][1] *= cr0;
            oacc[j][2] *= cr1; oacc[j][3] *= cr1;
        }

        // ---- o += P @ V ----
#pragma unroll
        for (int kc = 0; kc < 4; kc++) {
            uint32_t pa[4];
            {
                __half2 p0 = __floats2half2_rn(sacc[2 * kc][0], sacc[2 * kc][1]);
                __half2 p1 = __floats2half2_rn(sacc[2 * kc][2], sacc[2 * kc][3]);
                __half2 p2 = __floats2half2_rn(sacc[2 * kc + 1][0], sacc[2 * kc + 1][1]);
                __half2 p3 = __floats2half2_rn(sacc[2 * kc + 1][2], sacc[2 * kc + 1][3]);
                pa[0] = *(uint32_t*)&p0; pa[1] = *(uint32_t*)&p1;
                pa[2] = *(uint32_t*)&p2; pa[3] = *(uint32_t*)&p3;
            }
#pragma unroll
            for (int dp = 0; dp < 4; dp++) {
                uint32_t vb[4];
                LDMATRIX_X4_T(vb, VHs + swz128(kc * 16 + rVt, 2 * dp + cVo));
                MMA_F16(oacc[dp * 2],     pa, vb[0], vb[1]);
                MMA_F16(oacc[dp * 2 + 1], pa, vb[2], vb[3]);
            }
        }
        __syncthreads();
    }

    // ---- epilogue: o / l -> fp16 Ctx [B,T,D] ----
    const float i0 = 1.f / l0;
    const float i1 = 1.f / l1;
    __half* orow0 = Ctx + ((size_t)b * T_ + q0 + wid * 16 + (l >> 2)) * D_ + h * HD_;
    __half* orow1 = orow0 + 8 * D_;
#pragma unroll
    for (int j = 0; j < 8; j++) {
        *(__half2*)(orow0 + j * 8 + 2 * lq) =
            __floats2half2_rn(oacc[j][0] * i0, oacc[j][1] * i0);
        *(__half2*)(orow1 + j * 8 + 2 * lq) =
            __floats2half2_rn(oacc[j][2] * i1, oacc[j][3] * i1);
    }
}

// ---------------------------------------------------------------------------
// Launch
// ---------------------------------------------------------------------------
extern "C" void kernel_launch(void* const* d_in, const int* in_sizes, int n_in,
                              void* d_out, int out_size)
{
    const float* hs   = (const float*)d_in[0];
    const float* mask = (const float*)d_in[1];
    const float* Wq   = (const float*)d_in[2];
    const float* bq   = (const float*)d_in[3];
    const float* Wk   = (const float*)d_in[4];
    const float* bk   = (const float*)d_in[5];
    const float* Wv   = (const float*)d_in[6];
    const float* bv   = (const float*)d_in[7];
    const float* Wo   = (const float*)d_in[8];
    const float* bo   = (const float*)d_in[9];
    float* out = (float*)d_out;

    __half *HSh, *Wqh, *Wkh, *Wvh, *Woh, *Qhd, *Khd, *Vhd, *Ctxd;
    cudaGetSymbolAddress((void**)&HSh, g_HSh);
    cudaGetSymbolAddress((void**)&Wqh, g_Wqh);
    cudaGetSymbolAddress((void**)&Wkh, g_Wkh);
    cudaGetSymbolAddress((void**)&Wvh, g_Wvh);
    cudaGetSymbolAddress((void**)&Woh, g_Woh);
    cudaGetSymbolAddress((void**)&Qhd, g_Qh);
    cudaGetSymbolAddress((void**)&Khd, g_Kh);
    cudaGetSymbolAddress((void**)&Vhd, g_Vh);
    cudaGetSymbolAddress((void**)&Ctxd, g_Ctx);

    cudaFuncSetAttribute(gemm_f16<0>, cudaFuncAttributeMaxDynamicSharedMemorySize, GEMM_SMEM);
    cudaFuncSetAttribute(gemm_f16<1>, cudaFuncAttributeMaxDynamicSharedMemorySize, GEMM_SMEM);
    cudaFuncSetAttribute(attn_mma, cudaFuncAttributeMaxDynamicSharedMemorySize, ATTN_SMEM);

    // fp32 -> fp16 preconversion
    f32_to_f16<<<(M_ * D_ / 8 + 255) / 256, 256>>>(hs, HSh, M_ * D_ / 8);
    f32_to_f16<<<(D_ * D_ / 8 + 255) / 256, 256>>>(Wq, Wqh, D_ * D_ / 8);
    f32_to_f16<<<(D_ * D_ / 8 + 255) / 256, 256>>>(Wk, Wkh, D_ * D_ / 8);
    f32_to_f16<<<(D_ * D_ / 8 + 255) / 256, 256>>>(Wv, Wvh, D_ * D_ / 8);
    f32_to_f16<<<(D_ * D_ / 8 + 255) / 256, 256>>>(Wo, Woh, D_ * D_ / 8);

    const dim3 gemmGrid(D_ / 128, M_ / 128);   // (8, 32) = 256 CTAs
    const float scaling = 0.125f;              // HD^-0.5

    gemm_f16<1><<<gemmGrid, 256, GEMM_SMEM>>>(HSh, Wqh, bq, nullptr, Qhd, scaling);
    gemm_f16<1><<<gemmGrid, 256, GEMM_SMEM>>>(HSh, Wkh, bk, nullptr, Khd, 1.f);
    gemm_f16<1><<<gemmGrid, 256, GEMM_SMEM>>>(HSh, Wvh, bv, nullptr, Vhd, 1.f);

    attn_mma<<<dim3(T_ / 128, H_, B_), 256, ATTN_SMEM>>>(Qhd, Khd, Vhd, mask, Ctxd);

    gemm_f16<0><<<gemmGrid, 256, GEMM_SMEM>>>(Ctxd, Woh, bo, out, nullptr, 1.f);
}

// round 16
// speedup vs baseline: 9.3630x; 1.2367x over previous
#include <cuda_runtime.h>
#include <cuda_fp16.h>
#include <cstdint>

// Problem constants (MusicgenAttention: B=2, T=2048, D=1024, H=16, HD=64)
#define B_   2
#define T_   2048
#define D_   1024
#define H_   16
#define HD_  64
#define M_   (B_ * T_)
#define LOG2E 1.44269504088896340736f

// Scratch (device globals — allocation-free per harness rules)
__device__ __half g_HSh[M_ * D_];
__device__ __half g_Wqh[D_ * D_];
__device__ __half g_Wkh[D_ * D_];
__device__ __half g_Wvh[D_ * D_];
__device__ __half g_Woh[D_ * D_];
__device__ __half g_Qh[B_ * H_ * T_ * HD_];  // [B,H,T,HD]
__device__ __half g_Kh[B_ * H_ * T_ * HD_];
__device__ __half g_Vh[B_ * H_ * T_ * HD_];
__device__ __half g_Ctx[M_ * D_];            // [B,T,D] fp16
__device__ int    g_mask_nz;                 // 1 if any mask element nonzero

// ---------------------------------------------------------------------------
// PTX helpers (base sm_80+ — this toolchain's ptxas targets plain sm_103,
// which rejects tcgen05 'a'-features; legacy HMMA path)
// ---------------------------------------------------------------------------
__device__ __forceinline__ uint32_t smem_u32(const void* p) {
    uint32_t a;
    asm("{ .reg .u64 t; cvta.to.shared.u64 t, %1; cvt.u32.u64 %0, t; }" : "=r"(a) : "l"(p));
    return a;
}
__device__ __forceinline__ float ex2(float x) {
    float y; asm("ex2.approx.f32 %0, %1;" : "=f"(y) : "f"(x)); return y;
}

#define LDMATRIX_X4(r, addr)                                                   \
    asm volatile("ldmatrix.sync.aligned.m8n8.x4.shared.b16 {%0,%1,%2,%3}, [%4];" \
        : "=r"((r)[0]), "=r"((r)[1]), "=r"((r)[2]), "=r"((r)[3]) : "r"(addr))

#define LDMATRIX_X4_T(r, addr)                                                 \
    asm volatile("ldmatrix.sync.aligned.m8n8.x4.trans.shared.b16 {%0,%1,%2,%3}, [%4];" \
        : "=r"((r)[0]), "=r"((r)[1]), "=r"((r)[2]), "=r"((r)[3]) : "r"(addr))

#define MMA_F16(d, a, b0, b1)                                                  \
    asm volatile("mma.sync.aligned.m16n8k16.row.col.f32.f16.f16.f32 "          \
        "{%0,%1,%2,%3}, {%4,%5,%6,%7}, {%8,%9}, {%0,%1,%2,%3};"                \
        : "+f"((d)[0]), "+f"((d)[1]), "+f"((d)[2]), "+f"((d)[3])               \
        : "r"((a)[0]), "r"((a)[1]), "r"((a)[2]), "r"((a)[3]), "r"(b0), "r"(b1))

__device__ __forceinline__ void cp_async16(uint32_t dst, const void* src) {
    asm volatile("cp.async.cg.shared.global [%0], [%1], 16;" :: "r"(dst), "l"(src));
}
#define CP_COMMIT() asm volatile("cp.async.commit_group;" ::: "memory")
#define CP_WAIT(n)  asm volatile("cp.async.wait_group %0;" :: "n"(n) : "memory")

__device__ __forceinline__ uint32_t swz128(int r, int c) {   // 128B rows
    return (uint32_t)(r * 128 + ((c ^ (r & 7)) << 4));
}

// ---------------------------------------------------------------------------
// fp32 -> fp16 bulk converts + mask scan
// ---------------------------------------------------------------------------
__global__ __launch_bounds__(256)
void f32_to_f16(const float* __restrict__ in, __half* __restrict__ out, int n8)
{
    const int i = blockIdx.x * 256 + threadIdx.x;
    if (i < n8) {
        const float4 v0 = ((const float4*)in)[2 * i];
        const float4 v1 = ((const float4*)in)[2 * i + 1];
        __half2 h0 = __floats2half2_rn(v0.x, v0.y);
        __half2 h1 = __floats2half2_rn(v0.z, v0.w);
        __half2 h2 = __floats2half2_rn(v1.x, v1.y);
        __half2 h3 = __floats2half2_rn(v1.z, v1.w);
        ((uint4*)out)[i] = make_uint4(*(uint32_t*)&h0, *(uint32_t*)&h1,
                                      *(uint32_t*)&h2, *(uint32_t*)&h3);
    }
}

// 4 weight matrices in one launch (grid.y selects the matrix)
__global__ __launch_bounds__(256)
void w_to_f16(const float* __restrict__ w0, const float* __restrict__ w1,
              const float* __restrict__ w2, const float* __restrict__ w3,
              __half* __restrict__ o0, __half* __restrict__ o1,
              __half* __restrict__ o2, __half* __restrict__ o3)
{
    const float* in;
    __half* out;
    switch (blockIdx.y) {
        case 0:  in = w0; out = o0; break;
        case 1:  in = w1; out = o1; break;
        case 2:  in = w2; out = o2; break;
        default: in = w3; out = o3; break;
    }
    const int i = blockIdx.x * 256 + threadIdx.x;   // D*D/8 = 131072 -> grid.x=512
    const float4 v0 = ((const float4*)in)[2 * i];
    const float4 v1 = ((const float4*)in)[2 * i + 1];
    __half2 h0 = __floats2half2_rn(v0.x, v0.y);
    __half2 h1 = __floats2half2_rn(v0.z, v0.w);
    __half2 h2 = __floats2half2_rn(v1.x, v1.y);
    __half2 h3 = __floats2half2_rn(v1.z, v1.w);
    ((uint4*)out)[i] = make_uint4(*(uint32_t*)&h0, *(uint32_t*)&h1,
                                  *(uint32_t*)&h2, *(uint32_t*)&h3);
}

__global__ void mask_clear() { g_mask_nz = 0; }

__global__ __launch_bounds__(256)
void mask_scan(const float* __restrict__ m, int n4)
{
    const int i = blockIdx.x * 256 + threadIdx.x;
    if (i < n4) {
        const float4 v = ((const float4*)m)[i];
        if (v.x != 0.f || v.y != 0.f || v.z != 0.f || v.w != 0.f) g_mask_nz = 1;
    }
}

// ---------------------------------------------------------------------------
// 1-term fp16 GEMM (validated R11): C = (A @ W^T + bias) * scale
// Tile 128x128, BK=64, 2-stage cp.async pipeline, 256 threads, 2 CTAs/SM.
//   MODE 0: fp32 C0[m*D+n];  MODE 1: fp16 Ch at [B,H,T,HD]
// ---------------------------------------------------------------------------
#define GBK 64
#define GNIT (D_ / GBK)
#define GTILE_B (128 * GBK * 2)
#define GSTAGE_B (2 * GTILE_B)
#define GEMM_SMEM (2 * GSTAGE_B)

template <int MODE>
__global__ __launch_bounds__(256, 2)
void gemm_f16(const __half* __restrict__ A, const __half* __restrict__ W,
              const float* __restrict__ bias, float* __restrict__ C0,
              __half* __restrict__ Ch, float scale)
{
    extern __shared__ char smem[];
    const uint32_t sbase = smem_u32(smem);

    const int tid = threadIdx.x;
    const int wid = tid >> 5;
    const int l   = tid & 31;
    const int m0 = blockIdx.y * 128;
    const int n0 = blockIdx.x * 128;
    const int wm = (wid >> 1) * 32;
    const int wn = (wid & 1) * 64;

    float acc[2][8][4];
#pragma unroll
    for (int i = 0; i < 2; i++)
#pragma unroll
        for (int j = 0; j < 8; j++)
#pragma unroll
            for (int c = 0; c < 4; c++) acc[i][j][c] = 0.f;

#define GLOAD(it, s) do {                                                      \
        const uint32_t st = sbase + (s) * GSTAGE_B;                            \
        const int k0 = (it) * GBK;                                             \
        _Pragma("unroll")                                                      \
        for (int i = 0; i < 8; i++) {                                          \
            const int idx = tid + i * 256;                                     \
            const int tile = idx >> 10;                                        \
            const int r = (idx >> 3) & 127;                                    \
            const int c = idx & 7;                                             \
            const __half* src = (tile ? W + (size_t)(n0 + r) * D_              \
                                      : A + (size_t)(m0 + r) * D_) + k0 + c * 8; \
            cp_async16(st + tile * GTILE_B + swz128(r, c), src);               \
        }                                                                      \
    } while (0)

    GLOAD(0, 0); CP_COMMIT();

    for (int it = 0; it < GNIT; it++) {
        const int s = it & 1;
        CP_WAIT(0);
        __syncthreads();
        if (it + 1 < GNIT) { GLOAD(it + 1, s ^ 1); CP_COMMIT(); }

        const uint32_t As = sbase + s * GSTAGE_B;
        const uint32_t Ws = As + GTILE_B;

#pragma unroll
        for (int kc = 0; kc < 4; kc++) {
            uint32_t af[2][4];
            const int rA = wm + (l & 15);
            const int cA = 2 * kc + (l >> 4);
            LDMATRIX_X4(af[0], As + swz128(rA, cA));
            LDMATRIX_X4(af[1], As + swz128(rA + 16, cA));
#pragma unroll
            for (int jp = 0; jp < 4; jp++) {
                const int rB = wn + jp * 16 + (l & 7) + ((l >> 4) & 1) * 8;
                const int cB = 2 * kc + ((l >> 3) & 1);
                uint32_t bf[4];
                LDMATRIX_X4(bf, Ws + swz128(rB, cB));
                MMA_F16(acc[0][jp * 2],     af[0], bf[0], bf[1]);
                MMA_F16(acc[0][jp * 2 + 1], af[0], bf[2], bf[3]);
                MMA_F16(acc[1][jp * 2],     af[1], bf[0], bf[1]);
                MMA_F16(acc[1][jp * 2 + 1], af[1], bf[2], bf[3]);
            }
        }
    }

    const int qrow = l >> 2;
    const int qcol = (l & 3) * 2;
#pragma unroll
    for (int i = 0; i < 2; i++) {
        const int r0 = m0 + wm + i * 16 + qrow;
#pragma unroll
        for (int j = 0; j < 8; j++) {
            const int n = n0 + wn + j * 8 + qcol;
            const float b0 = bias[n], b1 = bias[n + 1];
#pragma unroll
            for (int half = 0; half < 2; half++) {
                const int m = r0 + half * 8;
                const float v0 = (acc[i][j][half * 2 + 0] + b0) * scale;
                const float v1 = (acc[i][j][half * 2 + 1] + b1) * scale;
                if (MODE == 0) {
                    *(float2*)(C0 + (size_t)m * D_ + n) = make_float2(v0, v1);
                } else {
                    const int b = m >> 11;
                    const int t = m & (T_ - 1);
                    const int h = n >> 6;
                    const int d = n & (HD_ - 1);
                    __half2 hv = __floats2half2_rn(v0, v1);
                    *(__half2*)(Ch + (((size_t)(b * H_ + h) * T_) + t) * HD_ + d) = hv;
                }
            }
        }
    }
}

// ---------------------------------------------------------------------------
// Tensor-core flash attention (1-term fp16, exp2-domain softmax).
// Q was pre-scaled by HD^-0.5 * log2(e), so softmax = exp2(s - max).
// Mask branch keyed off g_mask_nz (device-side scan; uniform branch).
// Grid (16,16,2), 256 threads, KC=64 keys/chunk, 2 CTAs/SM.
// ---------------------------------------------------------------------------
#define ATTN_SMEM 49152   // Q 16K + 2 KV stages of (K 8K + V 8K)

__global__ __launch_bounds__(256, 2)
void attn_mma(const __half* __restrict__ Qh, const __half* __restrict__ Kh,
              const __half* __restrict__ Vh, const float* __restrict__ mask,
              __half* __restrict__ Ctx)
{
    extern __shared__ char smem[];
    const uint32_t sb = smem_u32(smem);
    const int tid = threadIdx.x;
    const int wid = tid >> 5;
    const int l   = tid & 31;
    const int lq  = l & 3;
    const int b = blockIdx.z, h = blockIdx.y;
    const int q0 = blockIdx.x * 128;
    const size_t hb = (size_t)(b * H_ + h) * T_ * HD_;
    const int use_mask = g_mask_nz;

    const uint32_t QHs = sb, KV = sb + 16384;

#pragma unroll
    for (int i = 0; i < 4; i++) {
        const int idx = tid + i * 256;
        const int r = idx >> 3, c = idx & 7;
        cp_async16(QHs + swz128(r, c), Qh + hb + (size_t)(q0 + r) * HD_ + c * 8);
    }
    CP_COMMIT();
#pragma unroll
    for (int i = 0; i < 4; i++) {
        const int idx = tid + i * 256;
        const int tile = idx >> 9, r = (idx >> 3) & 63, c = idx & 7;
        const __half* src = (tile ? Vh : Kh) + hb + (size_t)r * HD_ + c * 8;
        cp_async16(KV + tile * 8192 + swz128(r, c), src);
    }
    CP_COMMIT();

    CP_WAIT(1);
    __syncthreads();

    uint32_t aq[4][4];
    {
        const int rA = wid * 16 + (l & 15);
#pragma unroll
        for (int kc = 0; kc < 4; kc++)
            LDMATRIX_X4(aq[kc], QHs + swz128(rA, 2 * kc + (l >> 4)));
    }

    float oacc[8][4];
#pragma unroll
    for (int j = 0; j < 8; j++)
#pragma unroll
        for (int e = 0; e < 4; e++) oacc[j][e] = 0.f;
    float m0 = -1e30f, m1 = -1e30f;
    float lsum0 = 0.f, lsum1 = 0.f;    // per-thread partial row sums

    const float* mr0 = mask + ((size_t)b * T_ + q0 + wid * 16 + (l >> 2)) * T_;
    const float* mr1 = mr0 + 8 * T_;

    const int rBk = (l & 7) + ((l >> 4) & 1) * 8;
    const int cBo = (l >> 3) & 1;
    const int rVt = (l & 7) + ((l >> 3) & 1) * 8;
    const int cVo = l >> 4;

    for (int kt = 0; kt < 32; kt++) {
        const int s = kt & 1;
        if (kt + 1 < 32) {
#pragma unroll
            for (int i = 0; i < 4; i++) {
                const int idx = tid + i * 256;
                const int tile = idx >> 9, r = (idx >> 3) & 63, c = idx & 7;
                const __half* src = (tile ? Vh : Kh) + hb +
                                    (size_t)((kt + 1) * 64 + r) * HD_ + c * 8;
                cp_async16(KV + (s ^ 1) * 16384 + tile * 8192 + swz128(r, c), src);
            }
            CP_COMMIT();
            CP_WAIT(1);
        } else {
            CP_WAIT(0);
        }
        __syncthreads();

        const uint32_t KHs = KV + s * 16384;
        const uint32_t VHs = KHs + 8192;

        // ---- S = Q K^T (already in log2 domain via Q pre-scale) ----
        float sacc[8][4];
#pragma unroll
        for (int j = 0; j < 8; j++)
#pragma unroll
            for (int e = 0; e < 4; e++) sacc[j][e] = 0.f;

#pragma unroll
        for (int kc = 0; kc < 4; kc++) {
#pragma unroll
            for (int jp = 0; jp < 4; jp++) {
                uint32_t kb[4];
                LDMATRIX_X4(kb, KHs + swz128(jp * 16 + rBk, 2 * kc + cBo));
                MMA_F16(sacc[jp * 2],     aq[kc], kb[0], kb[1]);
                MMA_F16(sacc[jp * 2 + 1], aq[kc], kb[2], kb[3]);
            }
        }

        // ---- +mask (only when mask has any nonzero; uniform branch) ----
        if (use_mask) {
            const int mb = kt * 64 + 2 * lq;
#pragma unroll
            for (int j = 0; j < 8; j++) {
                const float2 u0 = *(const float2*)(mr0 + mb + j * 8);
                const float2 u1 = *(const float2*)(mr1 + mb + j * 8);
                sacc[j][0] = fmaf(u0.x, LOG2E, sacc[j][0]);
                sacc[j][1] = fmaf(u0.y, LOG2E, sacc[j][1]);
                sacc[j][2] = fmaf(u1.x, LOG2E, sacc[j][2]);
                sacc[j][3] = fmaf(u1.y, LOG2E, sacc[j][3]);
            }
        }

        // ---- online softmax (exp2 domain, slim) ----
        float mx0 = -1e30f, mx1 = -1e30f;
#pragma unroll
        for (int j = 0; j < 8; j++) {
            mx0 = fmaxf(mx0, fmaxf(sacc[j][0], sacc[j][1]));
            mx1 = fmaxf(mx1, fmaxf(sacc[j][2], sacc[j][3]));
        }
        mx0 = fmaxf(mx0, __shfl_xor_sync(0xffffffffu, mx0, 1));
        mx0 = fmaxf(mx0, __shfl_xor_sync(0xffffffffu, mx0, 2));
        mx1 = fmaxf(mx1, __shfl_xor_sync(0xffffffffu, mx1, 1));
        mx1 = fmaxf(mx1, __shfl_xor_sync(0xffffffffu, mx1, 2));

        const float mn0 = fmaxf(m0, mx0);
        const float mn1 = fmaxf(m1, mx1);
        const float cr0 = ex2(m0 - mn0);
        const float cr1 = ex2(m1 - mn1);
        m0 = mn0; m1 = mn1;

        float rs0 = 0.f, rs1 = 0.f;
#pragma unroll
        for (int j = 0; j < 8; j++) {
            sacc[j][0] = ex2(sacc[j][0] - mn0);
            sacc[j][1] = ex2(sacc[j][1] - mn0);
            sacc[j][2] = ex2(sacc[j][2] - mn1);
            sacc[j][3] = ex2(sacc[j][3] - mn1);
            rs0 += sacc[j][0] + sacc[j][1];
            rs1 += sacc[j][2] + sacc[j][3];
        }
        lsum0 = lsum0 * cr0 + rs0;   // per-thread partial; quad-reduced at end
        lsum1 = lsum1 * cr1 + rs1;

        // rescale o only when some row max actually moved (warp-uniform skip)
        if (!__all_sync(0xffffffffu, (cr0 == 1.f) && (cr1 == 1.f))) {
#pragma unroll
            for (int j = 0; j < 8; j++) {
                oacc[j][0] *= cr0; oacc[j][1] *= cr0;
                oacc[j][2] *= cr1; oacc[j][3] *= cr1;
            }
        }

        // ---- o += P @ V ----
#pragma unroll
        for (int kc = 0; kc < 4; kc++) {
            uint32_t pa[4];
            {
                __half2 p0 = __floats2half2_rn(sacc[2 * kc][0], sacc[2 * kc][1]);
                __half2 p1 = __floats2half2_rn(sacc[2 * kc][2], sacc[2 * kc][3]);
                __half2 p2 = __floats2half2_rn(sacc[2 * kc + 1][0], sacc[2 * kc + 1][1]);
                __half2 p3 = __floats2half2_rn(sacc[2 * kc + 1][2], sacc[2 * kc + 1][3]);
                pa[0] = *(uint32_t*)&p0; pa[1] = *(uint32_t*)&p1;
                pa[2] = *(uint32_t*)&p2; pa[3] = *(uint32_t*)&p3;
            }
#pragma unroll
            for (int dp = 0; dp < 4; dp++) {
                uint32_t vb[4];
                LDMATRIX_X4_T(vb, VHs + swz128(kc * 16 + rVt, 2 * dp + cVo));
                MMA_F16(oacc[dp * 2],     pa, vb[0], vb[1]);
                MMA_F16(oacc[dp * 2 + 1], pa, vb[2], vb[3]);
            }
        }
        __syncthreads();
    }

    // ---- final l reduction + epilogue -> fp16 Ctx [B,T,D] ----
    lsum0 += __shfl_xor_sync(0xffffffffu, lsum0, 1);
    lsum0 += __shfl_xor_sync(0xffffffffu, lsum0, 2);
    lsum1 += __shfl_xor_sync(0xffffffffu, lsum1, 1);
    lsum1 += __shfl_xor_sync(0xffffffffu, lsum1, 2);
    const float i0 = 1.f / lsum0;
    const float i1 = 1.f / lsum1;
    __half* orow0 = Ctx + ((size_t)b * T_ + q0 + wid * 16 + (l >> 2)) * D_ + h * HD_;
    __half* orow1 = orow0 + 8 * D_;
#pragma unroll
    for (int j = 0; j < 8; j++) {
        *(__half2*)(orow0 + j * 8 + 2 * lq) =
            __floats2half2_rn(oacc[j][0] * i0, oacc[j][1] * i0);
        *(__half2*)(orow1 + j * 8 + 2 * lq) =
            __floats2half2_rn(oacc[j][2] * i1, oacc[j][3] * i1);
    }
}

// ---------------------------------------------------------------------------
// Launch
// ---------------------------------------------------------------------------
extern "C" void kernel_launch(void* const* d_in, const int* in_sizes, int n_in,
                              void* d_out, int out_size)
{
    const float* hs   = (const float*)d_in[0];
    const float* mask = (const float*)d_in[1];
    const float* Wq   = (const float*)d_in[2];
    const float* bq   = (const float*)d_in[3];
    const float* Wk   = (const float*)d_in[4];
    const float* bk   = (const float*)d_in[5];
    const float* Wv   = (const float*)d_in[6];
    const float* bv   = (const float*)d_in[7];
    const float* Wo   = (const float*)d_in[8];
    const float* bo   = (const float*)d_in[9];
    float* out = (float*)d_out;

    __half *HSh, *Wqh, *Wkh, *Wvh, *Woh, *Qhd, *Khd, *Vhd, *Ctxd;
    cudaGetSymbolAddress((void**)&HSh, g_HSh);
    cudaGetSymbolAddress((void**)&Wqh, g_Wqh);
    cudaGetSymbolAddress((void**)&Wkh, g_Wkh);
    cudaGetSymbolAddress((void**)&Wvh, g_Wvh);
    cudaGetSymbolAddress((void**)&Woh, g_Woh);
    cudaGetSymbolAddress((void**)&Qhd, g_Qh);
    cudaGetSymbolAddress((void**)&Khd, g_Kh);
    cudaGetSymbolAddress((void**)&Vhd, g_Vh);
    cudaGetSymbolAddress((void**)&Ctxd, g_Ctx);

    cudaFuncSetAttribute(gemm_f16<0>, cudaFuncAttributeMaxDynamicSharedMemorySize, GEMM_SMEM);
    cudaFuncSetAttribute(gemm_f16<1>, cudaFuncAttributeMaxDynamicSharedMemorySize, GEMM_SMEM);
    cudaFuncSetAttribute(attn_mma, cudaFuncAttributeMaxDynamicSharedMemorySize, ATTN_SMEM);

    // preconversion + mask scan
    f32_to_f16<<<(M_ * D_ / 8 + 255) / 256, 256>>>(hs, HSh, M_ * D_ / 8);
    w_to_f16<<<dim3(D_ * D_ / 8 / 256, 4), 256>>>(Wq, Wk, Wv, Wo, Wqh, Wkh, Wvh, Woh);
    mask_clear<<<1, 1>>>();
    mask_scan<<<(B_ * T_ * T_ / 4 + 255) / 256, 256>>>(mask, B_ * T_ * T_ / 4);

    const dim3 gemmGrid(D_ / 128, M_ / 128);   // (8, 32)
    const float scaling = 0.125f * LOG2E;      // HD^-0.5, pre-folded into log2 domain

    gemm_f16<1><<<gemmGrid, 256, GEMM_SMEM>>>(HSh, Wqh, bq, nullptr, Qhd, scaling);
    gemm_f16<1><<<gemmGrid, 256, GEMM_SMEM>>>(HSh, Wkh, bk, nullptr, Khd, 1.f);
    gemm_f16<1><<<gemmGrid, 256, GEMM_SMEM>>>(HSh, Wvh, bv, nullptr, Vhd, 1.f);

    attn_mma<<<dim3(T_ / 128, H_, B_), 256, ATTN_SMEM>>>(Qhd, Khd, Vhd, mask, Ctxd);

    gemm_f16<0><<<gemmGrid, 256, GEMM_SMEM>>>(Ctxd, Woh, bo, out, nullptr, 1.f);
}

// round 17
// speedup vs baseline: 9.5263x; 1.0174x over previous
#include <cuda_runtime.h>
#include <cuda_fp16.h>
#include <cstdint>

// Problem constants (MusicgenAttention: B=2, T=2048, D=1024, H=16, HD=64)
#define B_   2
#define T_   2048
#define D_   1024
#define H_   16
#define HD_  64
#define M_   (B_ * T_)
#define LOG2E 1.44269504088896340736f

// Scratch (device globals — allocation-free per harness rules)
__device__ __half g_HSh[M_ * D_];
__device__ __half g_Wqh[D_ * D_];
__device__ __half g_Wkh[D_ * D_];
__device__ __half g_Wvh[D_ * D_];
__device__ __half g_Woh[D_ * D_];
__device__ __half g_Qh[B_ * H_ * T_ * HD_];  // [B,H,T,HD]
__device__ __half g_Kh[B_ * H_ * T_ * HD_];
__device__ __half g_Vh[B_ * H_ * T_ * HD_];
__device__ __half g_Ctx[M_ * D_];            // [B,T,D] fp16
__device__ int    g_mask_nz;                 // 1 if any mask element nonzero

// ---------------------------------------------------------------------------
// PTX helpers (base sm_80+ — this toolchain's ptxas targets plain sm_103,
// which rejects tcgen05 'a'-features; legacy HMMA path)
// ---------------------------------------------------------------------------
__device__ __forceinline__ uint32_t smem_u32(const void* p) {
    uint32_t a;
    asm("{ .reg .u64 t; cvta.to.shared.u64 t, %1; cvt.u32.u64 %0, t; }" : "=r"(a) : "l"(p));
    return a;
}
__device__ __forceinline__ float ex2(float x) {
    float y; asm("ex2.approx.f32 %0, %1;" : "=f"(y) : "f"(x)); return y;
}

#define LDMATRIX_X4(r, addr)                                                   \
    asm volatile("ldmatrix.sync.aligned.m8n8.x4.shared.b16 {%0,%1,%2,%3}, [%4];" \
        : "=r"((r)[0]), "=r"((r)[1]), "=r"((r)[2]), "=r"((r)[3]) : "r"(addr))

#define LDMATRIX_X4_T(r, addr)                                                 \
    asm volatile("ldmatrix.sync.aligned.m8n8.x4.trans.shared.b16 {%0,%1,%2,%3}, [%4];" \
        : "=r"((r)[0]), "=r"((r)[1]), "=r"((r)[2]), "=r"((r)[3]) : "r"(addr))

#define MMA_F16(d, a, b0, b1)                                                  \
    asm volatile("mma.sync.aligned.m16n8k16.row.col.f32.f16.f16.f32 "          \
        "{%0,%1,%2,%3}, {%4,%5,%6,%7}, {%8,%9}, {%0,%1,%2,%3};"                \
        : "+f"((d)[0]), "+f"((d)[1]), "+f"((d)[2]), "+f"((d)[3])               \
        : "r"((a)[0]), "r"((a)[1]), "r"((a)[2]), "r"((a)[3]), "r"(b0), "r"(b1))

__device__ __forceinline__ void cp_async16(uint32_t dst, const void* src) {
    asm volatile("cp.async.cg.shared.global [%0], [%1], 16;" :: "r"(dst), "l"(src));
}
#define CP_COMMIT() asm volatile("cp.async.commit_group;" ::: "memory")
#define CP_WAIT(n)  asm volatile("cp.async.wait_group %0;" :: "n"(n) : "memory")

__device__ __forceinline__ uint32_t swz128(int r, int c) {   // 128B rows
    return (uint32_t)(r * 128 + ((c ^ (r & 7)) << 4));
}

// ---------------------------------------------------------------------------
// Fused prep: hs->fp16, 4 weights->fp16, mask nonzero scan. ONE launch.
//   blocks [0,2048):    hs convert      (M*D = 4M elems, 8/thread)
//   blocks [2048,4096):  weight convert  (4 x 1M elems, 8/thread)
//   blocks [4096,6144):  mask scan       (8.4M floats, 16/thread)
// ---------------------------------------------------------------------------
__device__ __forceinline__ void cvt8(const float* __restrict__ in,
                                     __half* __restrict__ out, int i) {
    const float4 v0 = ((const float4*)in)[2 * i];
    const float4 v1 = ((const float4*)in)[2 * i + 1];
    __half2 h0 = __floats2half2_rn(v0.x, v0.y);
    __half2 h1 = __floats2half2_rn(v0.z, v0.w);
    __half2 h2 = __floats2half2_rn(v1.x, v1.y);
    __half2 h3 = __floats2half2_rn(v1.z, v1.w);
    ((uint4*)out)[i] = make_uint4(*(uint32_t*)&h0, *(uint32_t*)&h1,
                                  *(uint32_t*)&h2, *(uint32_t*)&h3);
}

__global__ __launch_bounds__(256)
void prep_all(const float* __restrict__ hs,   const float* __restrict__ mask,
              const float* __restrict__ Wq,   const float* __restrict__ Wk,
              const float* __restrict__ Wv,   const float* __restrict__ Wo,
              __half* __restrict__ HSh, __half* __restrict__ Wqh,
              __half* __restrict__ Wkh, __half* __restrict__ Wvh,
              __half* __restrict__ Woh)
{
    const int bid = blockIdx.x;
    const int tid = threadIdx.x;

    if (bid < 2048) {
        // hs: M*D/8 = 524288 items
        cvt8(hs, HSh, bid * 256 + tid);
    } else if (bid < 4096) {
        // weights: 4 matrices x 131072 items
        const int idx = (bid - 2048) * 256 + tid;     // 0..524287
        const int w   = idx >> 17;                    // matrix id
        const int i   = idx & 131071;
        switch (w) {
            case 0:  cvt8(Wq, Wqh, i); break;
            case 1:  cvt8(Wk, Wkh, i); break;
            case 2:  cvt8(Wv, Wvh, i); break;
            default: cvt8(Wo, Woh, i); break;
        }
    } else {
        // mask scan: 16 floats per thread (ignore sign bit so -0.0 counts as 0)
        const int idx = (bid - 4096) * 256 + tid;     // 0..524287
        const uint4* p = (const uint4*)mask + idx * 4;
        uint32_t acc = 0;
#pragma unroll
        for (int u = 0; u < 4; u++) {
            const uint4 v = p[u];
            acc |= v.x | v.y | v.z | v.w;
        }
        if (acc & 0x7FFFFFFFu) g_mask_nz = 1;
    }
}

// ---------------------------------------------------------------------------
// 1-term fp16 GEMM (validated R11/R16): C = (A @ W^T + bias) * scale
// Tile 128x128, BK=64, 2-stage cp.async pipeline, 256 threads, 2 CTAs/SM.
//   MODE 0: fp32 C0[m*D+n];  MODE 1: fp16 Ch at [B,H,T,HD]
// ---------------------------------------------------------------------------
#define GBK 64
#define GNIT (D_ / GBK)
#define GTILE_B (128 * GBK * 2)
#define GSTAGE_B (2 * GTILE_B)
#define GEMM_SMEM (2 * GSTAGE_B)

template <int MODE>
__global__ __launch_bounds__(256, 2)
void gemm_f16(const __half* __restrict__ A, const __half* __restrict__ W,
              const float* __restrict__ bias, float* __restrict__ C0,
              __half* __restrict__ Ch, float scale)
{
    extern __shared__ char smem[];
    const uint32_t sbase = smem_u32(smem);

    const int tid = threadIdx.x;
    const int wid = tid >> 5;
    const int l   = tid & 31;
    const int m0 = blockIdx.y * 128;
    const int n0 = blockIdx.x * 128;
    const int wm = (wid >> 1) * 32;
    const int wn = (wid & 1) * 64;

    float acc[2][8][4];
#pragma unroll
    for (int i = 0; i < 2; i++)
#pragma unroll
        for (int j = 0; j < 8; j++)
#pragma unroll
            for (int c = 0; c < 4; c++) acc[i][j][c] = 0.f;

#define GLOAD(it, s) do {                                                      \
        const uint32_t st = sbase + (s) * GSTAGE_B;                            \
        const int k0 = (it) * GBK;                                             \
        _Pragma("unroll")                                                      \
        for (int i = 0; i < 8; i++) {                                          \
            const int idx = tid + i * 256;                                     \
            const int tile = idx >> 10;                                        \
            const int r = (idx >> 3) & 127;                                    \
            const int c = idx & 7;                                             \
            const __half* src = (tile ? W + (size_t)(n0 + r) * D_              \
                                      : A + (size_t)(m0 + r) * D_) + k0 + c * 8; \
            cp_async16(st + tile * GTILE_B + swz128(r, c), src);               \
        }                                                                      \
    } while (0)

    GLOAD(0, 0); CP_COMMIT();

    for (int it = 0; it < GNIT; it++) {
        const int s = it & 1;
        CP_WAIT(0);
        __syncthreads();
        if (it + 1 < GNIT) { GLOAD(it + 1, s ^ 1); CP_COMMIT(); }

        const uint32_t As = sbase + s * GSTAGE_B;
        const uint32_t Ws = As + GTILE_B;

#pragma unroll
        for (int kc = 0; kc < 4; kc++) {
            uint32_t af[2][4];
            const int rA = wm + (l & 15);
            const int cA = 2 * kc + (l >> 4);
            LDMATRIX_X4(af[0], As + swz128(rA, cA));
            LDMATRIX_X4(af[1], As + swz128(rA + 16, cA));
#pragma unroll
            for (int jp = 0; jp < 4; jp++) {
                const int rB = wn + jp * 16 + (l & 7) + ((l >> 4) & 1) * 8;
                const int cB = 2 * kc + ((l >> 3) & 1);
                uint32_t bf[4];
                LDMATRIX_X4(bf, Ws + swz128(rB, cB));
                MMA_F16(acc[0][jp * 2],     af[0], bf[0], bf[1]);
                MMA_F16(acc[0][jp * 2 + 1], af[0], bf[2], bf[3]);
                MMA_F16(acc[1][jp * 2],     af[1], bf[0], bf[1]);
                MMA_F16(acc[1][jp * 2 + 1], af[1], bf[2], bf[3]);
            }
        }
    }

    const int qrow = l >> 2;
    const int qcol = (l & 3) * 2;
#pragma unroll
    for (int i = 0; i < 2; i++) {
        const int r0 = m0 + wm + i * 16 + qrow;
#pragma unroll
        for (int j = 0; j < 8; j++) {
            const int n = n0 + wn + j * 8 + qcol;
            const float b0 = bias[n], b1 = bias[n + 1];
#pragma unroll
            for (int half = 0; half < 2; half++) {
                const int m = r0 + half * 8;
                const float v0 = (acc[i][j][half * 2 + 0] + b0) * scale;
                const float v1 = (acc[i][j][half * 2 + 1] + b1) * scale;
                if (MODE == 0) {
                    *(float2*)(C0 + (size_t)m * D_ + n) = make_float2(v0, v1);
                } else {
                    const int b = m >> 11;
                    const int t = m & (T_ - 1);
                    const int h = n >> 6;
                    const int d = n & (HD_ - 1);
                    __half2 hv = __floats2half2_rn(v0, v1);
                    *(__half2*)(Ch + (((size_t)(b * H_ + h) * T_) + t) * HD_ + d) = hv;
                }
            }
        }
    }
}

// ---------------------------------------------------------------------------
// Tensor-core flash attention (validated R16): 1-term fp16, exp2-domain
// softmax, mask skip via g_mask_nz. Grid (16,16,2), 256 threads, 2 CTAs/SM.
// ---------------------------------------------------------------------------
#define ATTN_SMEM 49152   // Q 16K + 2 KV stages of (K 8K + V 8K)

__global__ __launch_bounds__(256, 2)
void attn_mma(const __half* __restrict__ Qh, const __half* __restrict__ Kh,
              const __half* __restrict__ Vh, const float* __restrict__ mask,
              __half* __restrict__ Ctx)
{
    extern __shared__ char smem[];
    const uint32_t sb = smem_u32(smem);
    const int tid = threadIdx.x;
    const int wid = tid >> 5;
    const int l   = tid & 31;
    const int lq  = l & 3;
    const int b = blockIdx.z, h = blockIdx.y;
    const int q0 = blockIdx.x * 128;
    const size_t hb = (size_t)(b * H_ + h) * T_ * HD_;
    const int use_mask = g_mask_nz;

    const uint32_t QHs = sb, KV = sb + 16384;

#pragma unroll
    for (int i = 0; i < 4; i++) {
        const int idx = tid + i * 256;
        const int r = idx >> 3, c = idx & 7;
        cp_async16(QHs + swz128(r, c), Qh + hb + (size_t)(q0 + r) * HD_ + c * 8);
    }
    CP_COMMIT();
#pragma unroll
    for (int i = 0; i < 4; i++) {
        const int idx = tid + i * 256;
        const int tile = idx >> 9, r = (idx >> 3) & 63, c = idx & 7;
        const __half* src = (tile ? Vh : Kh) + hb + (size_t)r * HD_ + c * 8;
        cp_async16(KV + tile * 8192 + swz128(r, c), src);
    }
    CP_COMMIT();

    CP_WAIT(1);
    __syncthreads();

    uint32_t aq[4][4];
    {
        const int rA = wid * 16 + (l & 15);
#pragma unroll
        for (int kc = 0; kc < 4; kc++)
            LDMATRIX_X4(aq[kc], QHs + swz128(rA, 2 * kc + (l >> 4)));
    }

    float oacc[8][4];
#pragma unroll
    for (int j = 0; j < 8; j++)
#pragma unroll
        for (int e = 0; e < 4; e++) oacc[j][e] = 0.f;
    float m0 = -1e30f, m1 = -1e30f;
    float lsum0 = 0.f, lsum1 = 0.f;    // per-thread partial row sums

    const float* mr0 = mask + ((size_t)b * T_ + q0 + wid * 16 + (l >> 2)) * T_;
    const float* mr1 = mr0 + 8 * T_;

    const int rBk = (l & 7) + ((l >> 4) & 1) * 8;
    const int cBo = (l >> 3) & 1;
    const int rVt = (l & 7) + ((l >> 3) & 1) * 8;
    const int cVo = l >> 4;

    for (int kt = 0; kt < 32; kt++) {
        const int s = kt & 1;
        if (kt + 1 < 32) {
#pragma unroll
            for (int i = 0; i < 4; i++) {
                const int idx = tid + i * 256;
                const int tile = idx >> 9, r = (idx >> 3) & 63, c = idx & 7;
                const __half* src = (tile ? Vh : Kh) + hb +
                                    (size_t)((kt + 1) * 64 + r) * HD_ + c * 8;
                cp_async16(KV + (s ^ 1) * 16384 + tile * 8192 + swz128(r, c), src);
            }
            CP_COMMIT();
            CP_WAIT(1);
        } else {
            CP_WAIT(0);
        }
        __syncthreads();

        const uint32_t KHs = KV + s * 16384;
        const uint32_t VHs = KHs + 8192;

        // ---- S = Q K^T (log2 domain via Q pre-scale) ----
        float sacc[8][4];
#pragma unroll
        for (int j = 0; j < 8; j++)
#pragma unroll
            for (int e = 0; e < 4; e++) sacc[j][e] = 0.f;

#pragma unroll
        for (int kc = 0; kc < 4; kc++) {
#pragma unroll
            for (int jp = 0; jp < 4; jp++) {
                uint32_t kb[4];
                LDMATRIX_X4(kb, KHs + swz128(jp * 16 + rBk, 2 * kc + cBo));
                MMA_F16(sacc[jp * 2],     aq[kc], kb[0], kb[1]);
                MMA_F16(sacc[jp * 2 + 1], aq[kc], kb[2], kb[3]);
            }
        }

        // ---- +mask (uniform skip when mask is all-zero) ----
        if (use_mask) {
            const int mb = kt * 64 + 2 * lq;
#pragma unroll
            for (int j = 0; j < 8; j++) {
                const float2 u0 = *(const float2*)(mr0 + mb + j * 8);
                const float2 u1 = *(const float2*)(mr1 + mb + j * 8);
                sacc[j][0] = fmaf(u0.x, LOG2E, sacc[j][0]);
                sacc[j][1] = fmaf(u0.y, LOG2E, sacc[j][1]);
                sacc[j][2] = fmaf(u1.x, LOG2E, sacc[j][2]);
                sacc[j][3] = fmaf(u1.y, LOG2E, sacc[j][3]);
            }
        }

        // ---- online softmax (exp2 domain, slim) ----
        float mx0 = -1e30f, mx1 = -1e30f;
#pragma unroll
        for (int j = 0; j < 8; j++) {
            mx0 = fmaxf(mx0, fmaxf(sacc[j][0], sacc[j][1]));
            mx1 = fmaxf(mx1, fmaxf(sacc[j][2], sacc[j][3]));
        }
        mx0 = fmaxf(mx0, __shfl_xor_sync(0xffffffffu, mx0, 1));
        mx0 = fmaxf(mx0, __shfl_xor_sync(0xffffffffu, mx0, 2));
        mx1 = fmaxf(mx1, __shfl_xor_sync(0xffffffffu, mx1, 1));
        mx1 = fmaxf(mx1, __shfl_xor_sync(0xffffffffu, mx1, 2));

        const float mn0 = fmaxf(m0, mx0);
        const float mn1 = fmaxf(m1, mx1);
        const float cr0 = ex2(m0 - mn0);
        const float cr1 = ex2(m1 - mn1);
        m0 = mn0; m1 = mn1;

        float rs0 = 0.f, rs1 = 0.f;
#pragma unroll
        for (int j = 0; j < 8; j++) {
            sacc[j][0] = ex2(sacc[j][0] - mn0);
            sacc[j][1] = ex2(sacc[j][1] - mn0);
            sacc[j][2] = ex2(sacc[j][2] - mn1);
            sacc[j][3] = ex2(sacc[j][3] - mn1);
            rs0 += sacc[j][0] + sacc[j][1];
            rs1 += sacc[j][2] + sacc[j][3];
        }
        lsum0 = lsum0 * cr0 + rs0;
        lsum1 = lsum1 * cr1 + rs1;

        // rescale o only when some row max actually moved (warp-uniform skip)
        if (!__all_sync(0xffffffffu, (cr0 == 1.f) && (cr1 == 1.f))) {
#pragma unroll
            for (int j = 0; j < 8; j++) {
                oacc[j][0] *= cr0; oacc[j][1] *= cr0;
                oacc[j][2] *= cr1; oacc[j][3] *= cr1;
            }
        }

        // ---- o += P @ V ----
#pragma unroll
        for (int kc = 0; kc < 4; kc++) {
            uint32_t pa[4];
            {
                __half2 p0 = __floats2half2_rn(sacc[2 * kc][0], sacc[2 * kc][1]);
                __half2 p1 = __floats2half2_rn(sacc[2 * kc][2], sacc[2 * kc][3]);
                __half2 p2 = __floats2half2_rn(sacc[2 * kc + 1][0], sacc[2 * kc + 1][1]);
                __half2 p3 = __floats2half2_rn(sacc[2 * kc + 1][2], sacc[2 * kc + 1][3]);
                pa[0] = *(uint32_t*)&p0; pa[1] = *(uint32_t*)&p1;
                pa[2] = *(uint32_t*)&p2; pa[3] = *(uint32_t*)&p3;
            }
#pragma unroll
            for (int dp = 0; dp < 4; dp++) {
                uint32_t vb[4];
                LDMATRIX_X4_T(vb, VHs + swz128(kc * 16 + rVt, 2 * dp + cVo));
                MMA_F16(oacc[dp * 2],     pa, vb[0], vb[1]);
                MMA_F16(oacc[dp * 2 + 1], pa, vb[2], vb[3]);
            }
        }
        __syncthreads();
    }

    // ---- final l reduction + epilogue -> fp16 Ctx [B,T,D] ----
    lsum0 += __shfl_xor_sync(0xffffffffu, lsum0, 1);
    lsum0 += __shfl_xor_sync(0xffffffffu, lsum0, 2);
    lsum1 += __shfl_xor_sync(0xffffffffu, lsum1, 1);
    lsum1 += __shfl_xor_sync(0xffffffffu, lsum1, 2);
    const float i0 = 1.f / lsum0;
    const float i1 = 1.f / lsum1;
    __half* orow0 = Ctx + ((size_t)b * T_ + q0 + wid * 16 + (l >> 2)) * D_ + h * HD_;
    __half* orow1 = orow0 + 8 * D_;
#pragma unroll
    for (int j = 0; j < 8; j++) {
        *(__half2*)(orow0 + j * 8 + 2 * lq) =
            __floats2half2_rn(oacc[j][0] * i0, oacc[j][1] * i0);
        *(__half2*)(orow1 + j * 8 + 2 * lq) =
            __floats2half2_rn(oacc[j][2] * i1, oacc[j][3] * i1);
    }
}

// ---------------------------------------------------------------------------
// Launch
// ---------------------------------------------------------------------------
extern "C" void kernel_launch(void* const* d_in, const int* in_sizes, int n_in,
                              void* d_out, int out_size)
{
    const float* hs   = (const float*)d_in[0];
    const float* mask = (const float*)d_in[1];
    const float* Wq   = (const float*)d_in[2];
    const float* bq   = (const float*)d_in[3];
    const float* Wk   = (const float*)d_in[4];
    const float* bk   = (const float*)d_in[5];
    const float* Wv   = (const float*)d_in[6];
    const float* bv   = (const float*)d_in[7];
    const float* Wo   = (const float*)d_in[8];
    const float* bo   = (const float*)d_in[9];
    float* out = (float*)d_out;

    __half *HSh, *Wqh, *Wkh, *Wvh, *Woh, *Qhd, *Khd, *Vhd, *Ctxd;
    int* mask_nz_addr;
    cudaGetSymbolAddress((void**)&HSh, g_HSh);
    cudaGetSymbolAddress((void**)&Wqh, g_Wqh);
    cudaGetSymbolAddress((void**)&Wkh, g_Wkh);
    cudaGetSymbolAddress((void**)&Wvh, g_Wvh);
    cudaGetSymbolAddress((void**)&Woh, g_Woh);
    cudaGetSymbolAddress((void**)&Qhd, g_Qh);
    cudaGetSymbolAddress((void**)&Khd, g_Kh);
    cudaGetSymbolAddress((void**)&Vhd, g_Vh);
    cudaGetSymbolAddress((void**)&Ctxd, g_Ctx);
    cudaGetSymbolAddress((void**)&mask_nz_addr, g_mask_nz);

    cudaFuncSetAttribute(gemm_f16<0>, cudaFuncAttributeMaxDynamicSharedMemorySize, GEMM_SMEM);
    cudaFuncSetAttribute(gemm_f16<1>, cudaFuncAttributeMaxDynamicSharedMemorySize, GEMM_SMEM);
    cudaFuncSetAttribute(attn_mma, cudaFuncAttributeMaxDynamicSharedMemorySize, ATTN_SMEM);

    // fused prep: clear flag (async memset is graph-capturable), then one
    // launch converting hs + 4 weights and scanning the mask
    cudaMemsetAsync(mask_nz_addr, 0, sizeof(int));
    prep_all<<<6144, 256>>>(hs, mask, Wq, Wk, Wv, Wo, HSh, Wqh, Wkh, Wvh, Woh);

    const dim3 gemmGrid(D_ / 128, M_ / 128);   // (8, 32)
    const float scaling = 0.125f * LOG2E;      // HD^-0.5, pre-folded into log2 domain

    gemm_f16<1><<<gemmGrid, 256, GEMM_SMEM>>>(HSh, Wqh, bq, nullptr, Qhd, scaling);
    gemm_f16<1><<<gemmGrid, 256, GEMM_SMEM>>>(HSh, Wkh, bk, nullptr, Khd, 1.f);
    gemm_f16<1><<<gemmGrid, 256, GEMM_SMEM>>>(HSh, Wvh, bv, nullptr, Vhd, 1.f);

    attn_mma<<<dim3(T_ / 128, H_, B_), 256, ATTN_SMEM>>>(Qhd, Khd, Vhd, mask, Ctxd);

    gemm_f16<0><<<gemmGrid, 256, GEMM_SMEM>>>(Ctxd, Woh, bo, out, nullptr, 1.f);
}